// round 1
// baseline (speedup 1.0000x reference)
#include <cuda_runtime.h>
#include <math.h>

#define N_SITES 100000
#define DIM 128
#define HID 512
#define KVOL 343

// Scratch (device globals — no allocation allowed in kernel_launch)
__device__ float g_xln[N_SITES * DIM];    // post depthwise+LN   [N,128]
__device__ float g_h[N_SITES * HID];      // post pwconv1+GELU   [N,512]
__device__ float g_sumsq[HID];            // GRN sum of squares  [512]
__device__ float g_scale[HID];            // grn_g*nx + 1        [512]
__device__ float g_bias2[DIM];            // b2 + grn_b @ w2     [128]

// ---------------------------------------------------------------------------
// Kernel 1: sparse depthwise conv + LayerNorm. One block per site, 128 thr.
// Compacts valid (non-sentinel) neighbor indices first (~9 of 343 expected).
// ---------------------------------------------------------------------------
__global__ __launch_bounds__(128) void k_dwln(
    const float* __restrict__ feats, const int* __restrict__ nidx,
    const float* __restrict__ dw_w, const float* __restrict__ dw_b,
    const float* __restrict__ ln_g, const float* __restrict__ ln_b) {
  int site = blockIdx.x;
  int tid = threadIdx.x;
  __shared__ int s_k[KVOL];
  __shared__ int s_i[KVOL];
  __shared__ int s_cnt;
  if (tid == 0) s_cnt = 0;
  __syncthreads();
  const int* row = nidx + (long)site * KVOL;
  for (int k = tid; k < KVOL; k += 128) {
    int idx = row[k];
    if (idx < N_SITES) {
      int p = atomicAdd(&s_cnt, 1);
      s_k[p] = k;
      s_i[p] = idx;
    }
  }
  __syncthreads();
  float acc = dw_b[tid];
  int cnt = s_cnt;
  for (int v = 0; v < cnt; v++) {
    int k = s_k[v];
    int idx = s_i[v];
    acc += __ldg(&feats[(long)idx * DIM + tid]) * dw_w[k * DIM + tid];
  }
  // LayerNorm over the 128 channels (block reduce)
  float s1 = acc, s2 = acc * acc;
  #pragma unroll
  for (int o = 16; o > 0; o >>= 1) {
    s1 += __shfl_xor_sync(0xffffffffu, s1, o);
    s2 += __shfl_xor_sync(0xffffffffu, s2, o);
  }
  __shared__ float r1[4], r2[4];
  int w = tid >> 5, l = tid & 31;
  if (l == 0) { r1[w] = s1; r2[w] = s2; }
  __syncthreads();
  s1 = r1[0] + r1[1] + r1[2] + r1[3];
  s2 = r2[0] + r2[1] + r2[2] + r2[3];
  float mu = s1 * (1.f / 128.f);
  float var = s2 * (1.f / 128.f) - mu * mu;
  float rstd = rsqrtf(var + 1e-6f);
  g_xln[(long)site * DIM + tid] = (acc - mu) * rstd * ln_g[tid] + ln_b[tid];
}

__global__ void k_zero() { g_sumsq[threadIdx.x] = 0.f; }

// ---------------------------------------------------------------------------
// Kernel 2: h = GELU(xln @ w1 + b1), plus per-channel sum of squares.
// Tile 64x64, K-tiles of 64, 128 threads, 8x4 register blocking.
// ---------------------------------------------------------------------------
__global__ __launch_bounds__(128) void k_gemm1(
    const float* __restrict__ w1, const float* __restrict__ b1) {
  __shared__ float As[64][68];   // padded to dodge bank conflicts
  __shared__ float Bs[64][64];
  __shared__ float s_ss[64];
  int tid = threadIdx.x;
  int tx = tid & 15, ty = tid >> 4;
  int m0 = blockIdx.x * 64;
  int n0 = blockIdx.y * 64;
  float acc[8][4];
  #pragma unroll
  for (int j = 0; j < 8; j++)
    #pragma unroll
    for (int q = 0; q < 4; q++) acc[j][q] = 0.f;

  for (int kt = 0; kt < DIM; kt += 64) {
    #pragma unroll
    for (int p = 0; p < 8; p++) {
      int r = p * 8 + ty;
      int gr = m0 + r;
      float4 v = make_float4(0.f, 0.f, 0.f, 0.f);
      if (gr < N_SITES) v = *(const float4*)&g_xln[gr * DIM + kt + tx * 4];
      *(float4*)&As[r][tx * 4] = v;
      int k = p * 8 + ty;
      *(float4*)&Bs[k][tx * 4] = *(const float4*)&w1[(kt + k) * HID + n0 + tx * 4];
    }
    __syncthreads();
    #pragma unroll 8
    for (int k = 0; k < 64; k++) {
      float4 b4 = *(float4*)&Bs[k][tx * 4];
      float a[8];
      #pragma unroll
      for (int j = 0; j < 8; j++) a[j] = As[ty * 8 + j][k];
      #pragma unroll
      for (int j = 0; j < 8; j++) {
        acc[j][0] += a[j] * b4.x;
        acc[j][1] += a[j] * b4.y;
        acc[j][2] += a[j] * b4.z;
        acc[j][3] += a[j] * b4.w;
      }
    }
    __syncthreads();
  }
  if (tid < 64) s_ss[tid] = 0.f;
  __syncthreads();
  float4 bb = *(const float4*)&b1[n0 + tx * 4];
  float c0 = 0.f, c1 = 0.f, c2 = 0.f, c3 = 0.f;
  #pragma unroll
  for (int j = 0; j < 8; j++) {
    int gr = m0 + ty * 8 + j;
    if (gr < N_SITES) {
      float x0 = acc[j][0] + bb.x, x1 = acc[j][1] + bb.y;
      float x2 = acc[j][2] + bb.z, x3 = acc[j][3] + bb.w;
      float g0 = 0.5f * x0 * (1.f + erff(x0 * 0.70710678118654752f));
      float g1 = 0.5f * x1 * (1.f + erff(x1 * 0.70710678118654752f));
      float g2 = 0.5f * x2 * (1.f + erff(x2 * 0.70710678118654752f));
      float g3 = 0.5f * x3 * (1.f + erff(x3 * 0.70710678118654752f));
      *(float4*)&g_h[gr * HID + n0 + tx * 4] = make_float4(g0, g1, g2, g3);
      c0 += g0 * g0; c1 += g1 * g1; c2 += g2 * g2; c3 += g3 * g3;
    }
  }
  atomicAdd(&s_ss[tx * 4 + 0], c0);
  atomicAdd(&s_ss[tx * 4 + 1], c1);
  atomicAdd(&s_ss[tx * 4 + 2], c2);
  atomicAdd(&s_ss[tx * 4 + 3], c3);
  __syncthreads();
  if (tid < 64) atomicAdd(&g_sumsq[n0 + tid], s_ss[tid]);
}

// ---------------------------------------------------------------------------
// Kernel 3: GRN finalize. scale[c] = grn_g[c]*nx[c] + 1;
// bias2[j] = b2[j] + sum_c grn_b[c] * w2[c][j]  (grn_b folded into bias).
// ---------------------------------------------------------------------------
__global__ __launch_bounds__(512) void k_grn(
    const float* __restrict__ grn_g, const float* __restrict__ grn_b,
    const float* __restrict__ w2, const float* __restrict__ b2) {
  int t = threadIdx.x;
  float gx = sqrtf(g_sumsq[t]);
  __shared__ float red[16];
  float s = gx;
  #pragma unroll
  for (int o = 16; o > 0; o >>= 1) s += __shfl_xor_sync(0xffffffffu, s, o);
  if ((t & 31) == 0) red[t >> 5] = s;
  __syncthreads();
  if (t < 16) {
    float v = red[t];
    #pragma unroll
    for (int o = 8; o > 0; o >>= 1) v += __shfl_xor_sync(0x0000ffffu, v, o);
    if (t == 0) red[0] = v;
  }
  __syncthreads();
  float mean = red[0] * (1.f / 512.f);
  float nx = gx / (mean + 1e-6f);
  g_scale[t] = grn_g[t] * nx + 1.f;
  if (t < DIM) {
    float s2 = b2[t];
    for (int c = 0; c < HID; c++) s2 += grn_b[c] * w2[c * DIM + t];
    g_bias2[t] = s2;
  }
}

// ---------------------------------------------------------------------------
// Kernel 4: out = (h * scale) @ w2 + bias2 + feats.
// scale folded into B tile at load (per-k scalar).
// ---------------------------------------------------------------------------
__global__ __launch_bounds__(128) void k_gemm2(
    const float* __restrict__ w2, const float* __restrict__ feats,
    float* __restrict__ out) {
  __shared__ float As[64][68];
  __shared__ float Bs[64][64];
  int tid = threadIdx.x;
  int tx = tid & 15, ty = tid >> 4;
  int m0 = blockIdx.x * 64;
  int n0 = blockIdx.y * 64;
  float acc[8][4];
  #pragma unroll
  for (int j = 0; j < 8; j++)
    #pragma unroll
    for (int q = 0; q < 4; q++) acc[j][q] = 0.f;

  for (int kt = 0; kt < HID; kt += 64) {
    #pragma unroll
    for (int p = 0; p < 8; p++) {
      int r = p * 8 + ty;
      int gr = m0 + r;
      float4 v = make_float4(0.f, 0.f, 0.f, 0.f);
      if (gr < N_SITES) v = *(const float4*)&g_h[gr * HID + kt + tx * 4];
      *(float4*)&As[r][tx * 4] = v;
      int k = p * 8 + ty;
      float sc = g_scale[kt + k];
      float4 wv = *(const float4*)&w2[(kt + k) * DIM + n0 + tx * 4];
      wv.x *= sc; wv.y *= sc; wv.z *= sc; wv.w *= sc;
      *(float4*)&Bs[k][tx * 4] = wv;
    }
    __syncthreads();
    #pragma unroll 8
    for (int k = 0; k < 64; k++) {
      float4 b4 = *(float4*)&Bs[k][tx * 4];
      float a[8];
      #pragma unroll
      for (int j = 0; j < 8; j++) a[j] = As[ty * 8 + j][k];
      #pragma unroll
      for (int j = 0; j < 8; j++) {
        acc[j][0] += a[j] * b4.x;
        acc[j][1] += a[j] * b4.y;
        acc[j][2] += a[j] * b4.z;
        acc[j][3] += a[j] * b4.w;
      }
    }
    __syncthreads();
  }
  float4 bb = *(const float4*)&g_bias2[n0 + tx * 4];
  #pragma unroll
  for (int j = 0; j < 8; j++) {
    int gr = m0 + ty * 8 + j;
    if (gr < N_SITES) {
      float4 f = *(const float4*)&feats[gr * DIM + n0 + tx * 4];
      float4 o;
      o.x = acc[j][0] + bb.x + f.x;
      o.y = acc[j][1] + bb.y + f.y;
      o.z = acc[j][2] + bb.z + f.z;
      o.w = acc[j][3] + bb.w + f.w;
      *(float4*)&out[gr * DIM + n0 + tx * 4] = o;
    }
  }
}

extern "C" void kernel_launch(void* const* d_in, const int* in_sizes, int n_in,
                              void* d_out, int out_size) {
  const float* feats = (const float*)d_in[0];
  const int*   nidx  = (const int*)d_in[1];
  const float* dw_w  = (const float*)d_in[2];
  const float* dw_b  = (const float*)d_in[3];
  const float* ln_g  = (const float*)d_in[4];
  const float* ln_b  = (const float*)d_in[5];
  const float* w1    = (const float*)d_in[6];
  const float* b1    = (const float*)d_in[7];
  const float* grn_g = (const float*)d_in[8];
  const float* grn_b = (const float*)d_in[9];
  const float* w2    = (const float*)d_in[10];
  const float* b2    = (const float*)d_in[11];
  float* out = (float*)d_out;

  const int MB = (N_SITES + 63) / 64;  // 1563
  k_dwln<<<N_SITES, 128>>>(feats, nidx, dw_w, dw_b, ln_g, ln_b);
  k_zero<<<1, HID>>>();
  k_gemm1<<<dim3(MB, HID / 64), 128>>>(w1, b1);
  k_grn<<<1, HID>>>(grn_g, grn_b, w2, b2);
  k_gemm2<<<dim3(MB, DIM / 64), 128>>>(w2, feats, out);
}

// round 3
// speedup vs baseline: 1.4611x; 1.4611x over previous
#include <cuda_runtime.h>
#include <cuda_bf16.h>
#include <math.h>
#include <stdint.h>

#define N_SITES 100000
#define DIM 128
#define HID 512
#define KVOL 343

// ---------------- scratch (device globals; no runtime allocation) ----------
__device__ __align__(16) __nv_bfloat16 g_x_hi[N_SITES * DIM];
__device__ __align__(16) __nv_bfloat16 g_x_lo[N_SITES * DIM];
__device__ __align__(16) __nv_bfloat16 g_h_hi[(size_t)N_SITES * HID];
__device__ __align__(16) __nv_bfloat16 g_h_lo[(size_t)N_SITES * HID];
__device__ __align__(16) __nv_bfloat16 g_w1t_hi[HID * DIM];  // [n][k]
__device__ __align__(16) __nv_bfloat16 g_w1t_lo[HID * DIM];
__device__ __align__(16) __nv_bfloat16 g_w2s_hi[DIM * HID];  // [n][k] (scaled)
__device__ __align__(16) __nv_bfloat16 g_w2s_lo[DIM * HID];
__device__ float g_sumsq[HID];
__device__ float g_scale[HID];
__device__ float g_bias2[DIM];

// ---------------- PTX helpers ----------------------------------------------
__device__ __forceinline__ uint32_t smem_u32(const void* p) {
  uint32_t a;
  asm("{ .reg .u64 t; cvta.to.shared.u64 t, %1; cvt.u32.u64 %0, t; }"
      : "=r"(a) : "l"(p));
  return a;
}

__device__ __forceinline__ void cpa16(uint32_t dst, const void* src, uint32_t sz) {
  asm volatile("cp.async.cg.shared.global [%0], [%1], 16, %2;"
               ::"r"(dst), "l"(src), "r"(sz) : "memory");
}
#define CP_COMMIT() asm volatile("cp.async.commit_group;" ::: "memory")
#define CP_WAIT1() asm volatile("cp.async.wait_group 1;" ::: "memory")
#define CP_WAIT0() asm volatile("cp.async.wait_group 0;" ::: "memory")

__device__ __forceinline__ void ldsm4(uint32_t* r, uint32_t addr) {
  asm volatile("ldmatrix.sync.aligned.m8n8.x4.shared.b16 {%0,%1,%2,%3}, [%4];"
               : "=r"(r[0]), "=r"(r[1]), "=r"(r[2]), "=r"(r[3]) : "r"(addr));
}

__device__ __forceinline__ void mma16816(float* d, const uint32_t* a, const uint32_t* b) {
  asm volatile(
      "mma.sync.aligned.m16n8k16.row.col.f32.bf16.bf16.f32 "
      "{%0,%1,%2,%3}, {%4,%5,%6,%7}, {%8,%9}, {%0,%1,%2,%3};"
      : "+f"(d[0]), "+f"(d[1]), "+f"(d[2]), "+f"(d[3])
      : "r"(a[0]), "r"(a[1]), "r"(a[2]), "r"(a[3]), "r"(b[0]), "r"(b[1]));
}

// ---------------- gemm tiling constants -------------------------------------
// Block tile 128x128, K-chunk 32, 8 warps (2 m x 4 n), warp tile 64x32.
// Stage: Ah | Al | Bh | Bl, each 128 rows x 32 bf16 (64B/row), 8KB each.
#define OFF_AH 0
#define OFF_AL 8192
#define OFF_BH 16384
#define OFF_BL 24576
#define STAGE 32768
#define NSTAGE 3
#define SMEM_DYN (NSTAGE * STAGE)  // 98304
#define STG_STRIDE 132             // fp32 epilogue stage row stride

// swizzled offset for (row, 16B-chunk c) in a 128x32 bf16 tile
__device__ __forceinline__ uint32_t swz(uint32_t r, uint32_t c) {
  return r * 64 + ((c ^ ((r >> 1) & 3)) << 4);
}

// Load one 128x32 bf16 tile (rows row0.., zero-fill past rowmax) via cp.async.
__device__ __forceinline__ void ld_tile(uint32_t sbase, const __nv_bfloat16* __restrict__ src,
                                        int row0, int rowmax, int ld, int k0, int tid) {
#pragma unroll
  for (int i = 0; i < 2; i++) {
    int g = i * 256 + tid;
    int r = g >> 2, c = g & 3;
    int gr = row0 + r;
    uint32_t sz = (gr < rowmax) ? 16u : 0u;
    int grc = (gr < rowmax) ? gr : 0;
    cpa16(sbase + swz(r, c), src + (size_t)grc * ld + k0 + c * 8, sz);
  }
}

// Compute one K=32 chunk: 2 k-steps x (4 m-tiles x 4 n-tiles) x 3 products.
__device__ __forceinline__ void mma_chunk(float acc[4][4][4], uint32_t ssb,
                                          int wm, int wn, int lane) {
  uint32_t a_r = wm * 64 + (lane & 15);
  uint32_t a_c = (uint32_t)(lane >> 4);
  uint32_t b_r = wn * 32 + ((lane >> 4) << 3) + (lane & 7);
  uint32_t b_c = (uint32_t)((lane >> 3) & 1);
#pragma unroll
  for (int ks = 0; ks < 2; ks++) {
    uint32_t ah[4][4], al[4][4], bh[2][4], bl[2][4];
#pragma unroll
    for (int mt = 0; mt < 4; mt++) {
      uint32_t off = swz(a_r + mt * 16, ks * 2 + a_c);
      ldsm4(ah[mt], ssb + OFF_AH + off);
      ldsm4(al[mt], ssb + OFF_AL + off);
    }
#pragma unroll
    for (int np = 0; np < 2; np++) {
      uint32_t off = swz(b_r + np * 16, ks * 2 + b_c);
      ldsm4(bh[np], ssb + OFF_BH + off);
      ldsm4(bl[np], ssb + OFF_BL + off);
    }
#pragma unroll
    for (int mt = 0; mt < 4; mt++)
#pragma unroll
      for (int nt = 0; nt < 4; nt++) {
        const uint32_t* bhp = &bh[nt >> 1][(nt & 1) * 2];
        const uint32_t* blp = &bl[nt >> 1][(nt & 1) * 2];
        mma16816(acc[mt][nt], ah[mt], bhp);
        mma16816(acc[mt][nt], al[mt], bhp);
        mma16816(acc[mt][nt], ah[mt], blp);
      }
  }
}

// Write C fragments into fp32 smem staging (row-major with pad stride).
__device__ __forceinline__ void frag_to_stg(float* stg, float acc[4][4][4],
                                            int wm, int wn, int lane) {
#pragma unroll
  for (int mt = 0; mt < 4; mt++)
#pragma unroll
    for (int nt = 0; nt < 4; nt++) {
      int m = wm * 64 + mt * 16 + (lane >> 2);
      int n = wn * 32 + nt * 8 + (lane & 3) * 2;
      *(float2*)&stg[m * STG_STRIDE + n] = make_float2(acc[mt][nt][0], acc[mt][nt][1]);
      *(float2*)&stg[(m + 8) * STG_STRIDE + n] = make_float2(acc[mt][nt][2], acc[mt][nt][3]);
    }
}

// ---------------------------------------------------------------------------
// Kernel 1: sparse depthwise conv + LayerNorm -> bf16 hi/lo split
// ---------------------------------------------------------------------------
__global__ __launch_bounds__(128) void k_dwln(
    const float* __restrict__ feats, const int* __restrict__ nidx,
    const float* __restrict__ dw_w, const float* __restrict__ dw_b,
    const float* __restrict__ ln_g, const float* __restrict__ ln_b) {
  int site = blockIdx.x;
  int tid = threadIdx.x;
  __shared__ int s_k[KVOL];
  __shared__ int s_i[KVOL];
  __shared__ int s_cnt;
  if (tid == 0) s_cnt = 0;
  __syncthreads();
  const int* row = nidx + (size_t)site * KVOL;
  for (int k = tid; k < KVOL; k += 128) {
    int idx = row[k];
    if (idx < N_SITES) {
      int p = atomicAdd(&s_cnt, 1);
      s_k[p] = k;
      s_i[p] = idx;
    }
  }
  __syncthreads();
  float acc = dw_b[tid];
  int cnt = s_cnt;
  for (int v = 0; v < cnt; v++) {
    int k = s_k[v];
    int idx = s_i[v];
    acc += __ldg(&feats[(size_t)idx * DIM + tid]) * dw_w[k * DIM + tid];
  }
  float s1 = acc, s2 = acc * acc;
#pragma unroll
  for (int o = 16; o > 0; o >>= 1) {
    s1 += __shfl_xor_sync(0xffffffffu, s1, o);
    s2 += __shfl_xor_sync(0xffffffffu, s2, o);
  }
  __shared__ float r1[4], r2[4];
  int w = tid >> 5, l = tid & 31;
  if (l == 0) { r1[w] = s1; r2[w] = s2; }
  __syncthreads();
  s1 = r1[0] + r1[1] + r1[2] + r1[3];
  s2 = r2[0] + r2[1] + r2[2] + r2[3];
  float mu = s1 * (1.f / 128.f);
  float var = s2 * (1.f / 128.f) - mu * mu;
  float rstd = rsqrtf(var + 1e-6f);
  float val = (acc - mu) * rstd * ln_g[tid] + ln_b[tid];
  __nv_bfloat16 hi = __float2bfloat16(val);
  __nv_bfloat16 lo = __float2bfloat16(val - __bfloat162float(hi));
  g_x_hi[site * DIM + tid] = hi;
  g_x_lo[site * DIM + tid] = lo;
}

__global__ void k_zero() { g_sumsq[threadIdx.x] = 0.f; }

// w1 [128,512] -> transposed split w1t [n][k]
__global__ __launch_bounds__(256) void k_prepw1(const float* __restrict__ w1) {
  int i = blockIdx.x * 256 + threadIdx.x;  // 0..65535
  int n = i >> 7, k = i & 127;
  float v = w1[k * HID + n];
  __nv_bfloat16 hi = __float2bfloat16(v);
  g_w1t_hi[i] = hi;
  g_w1t_lo[i] = __float2bfloat16(v - __bfloat162float(hi));
}

// ---------------------------------------------------------------------------
// GEMM1: h = GELU(xln @ w1 + b1)  (+ per-channel sumsq for GRN)
// ---------------------------------------------------------------------------
__global__ __launch_bounds__(256, 1) void k_gemm1(const float* __restrict__ b1) {
  extern __shared__ char smem[];
  __shared__ float s_ss[128];
  uint32_t sb = smem_u32(smem);
  int tid = threadIdx.x, lane = tid & 31, w = tid >> 5;
  int wm = w & 1, wn = w >> 1;
  int m0 = blockIdx.x * 128, n0 = blockIdx.y * 128;
  if (tid < 128) s_ss[tid] = 0.f;

  float acc[4][4][4] = {};
  const int CH = DIM / 32;  // 4

  // prologue: prefetch chunks 0,1
#pragma unroll
  for (int c = 0; c < 2; c++) {
    uint32_t ssb = sb + (c % NSTAGE) * STAGE;
    ld_tile(ssb + OFF_AH, g_x_hi, m0, N_SITES, DIM, c * 32, tid);
    ld_tile(ssb + OFF_AL, g_x_lo, m0, N_SITES, DIM, c * 32, tid);
    ld_tile(ssb + OFF_BH, g_w1t_hi, n0, HID, DIM, c * 32, tid);
    ld_tile(ssb + OFF_BL, g_w1t_lo, n0, HID, DIM, c * 32, tid);
    CP_COMMIT();
  }
#pragma unroll 1
  for (int c = 0; c < CH; c++) {
    CP_WAIT1();
    __syncthreads();
    mma_chunk(acc, sb + (c % NSTAGE) * STAGE, wm, wn, lane);
    int pc = c + 2;
    if (pc < CH) {
      uint32_t ssb = sb + (pc % NSTAGE) * STAGE;
      ld_tile(ssb + OFF_AH, g_x_hi, m0, N_SITES, DIM, pc * 32, tid);
      ld_tile(ssb + OFF_AL, g_x_lo, m0, N_SITES, DIM, pc * 32, tid);
      ld_tile(ssb + OFF_BH, g_w1t_hi, n0, HID, DIM, pc * 32, tid);
      ld_tile(ssb + OFF_BL, g_w1t_lo, n0, HID, DIM, pc * 32, tid);
    }
    CP_COMMIT();
  }
  CP_WAIT0();
  __syncthreads();  // all warps done reading stages before stg overwrite

  float* stg = (float*)smem;
  frag_to_stg(stg, acc, wm, wn, lane);
  __syncthreads();

  // ---- pass 2: bias + GELU + sumsq + hi/lo store (coalesced) ---------------
  float ss[8] = {0, 0, 0, 0, 0, 0, 0, 0};
  int ci = (tid & 15) * 8;
  float4 bb0 = *(const float4*)&b1[n0 + ci];
  float4 bb1 = *(const float4*)&b1[n0 + ci + 4];
  float bias[8] = {bb0.x, bb0.y, bb0.z, bb0.w, bb1.x, bb1.y, bb1.z, bb1.w};
#pragma unroll
  for (int p = 0; p < 8; p++) {
    int rr = p * 16 + (tid >> 4);
    int m = m0 + rr;
    if (m < N_SITES) {
      float4 v0 = *(float4*)&stg[rr * STG_STRIDE + ci];
      float4 v1 = *(float4*)&stg[rr * STG_STRIDE + ci + 4];
      float v[8] = {v0.x, v0.y, v0.z, v0.w, v1.x, v1.y, v1.z, v1.w};
      union { __nv_bfloat16 b[8]; uint4 u; } uh, ul;
#pragma unroll
      for (int e = 0; e < 8; e++) {
        float x = v[e] + bias[e];
        float g = 0.5f * x * (1.f + erff(x * 0.70710678118654752f));
        ss[e] += g * g;
        uh.b[e] = __float2bfloat16(g);
        ul.b[e] = __float2bfloat16(g - __bfloat162float(uh.b[e]));
      }
      *(uint4*)&g_h_hi[(size_t)m * HID + n0 + ci] = uh.u;
      *(uint4*)&g_h_lo[(size_t)m * HID + n0 + ci] = ul.u;
    }
  }
#pragma unroll
  for (int e = 0; e < 8; e++) ss[e] += __shfl_xor_sync(0xffffffffu, ss[e], 16);
  if (lane < 16) {
#pragma unroll
    for (int e = 0; e < 8; e++) atomicAdd(&s_ss[ci + e], ss[e]);
  }
  __syncthreads();
  if (tid < 128) atomicAdd(&g_sumsq[n0 + tid], s_ss[tid]);
}

// ---------------------------------------------------------------------------
// GRN scale: scale[c] = grn_g[c] * nx[c] + 1
// ---------------------------------------------------------------------------
__global__ __launch_bounds__(512) void k_grn(const float* __restrict__ grn_g) {
  int t = threadIdx.x;
  float gx = sqrtf(g_sumsq[t]);
  __shared__ float red[16];
  float s = gx;
#pragma unroll
  for (int o = 16; o > 0; o >>= 1) s += __shfl_xor_sync(0xffffffffu, s, o);
  if ((t & 31) == 0) red[t >> 5] = s;
  __syncthreads();
  if (t < 16) {
    float v = red[t];
#pragma unroll
    for (int o = 8; o > 0; o >>= 1) v += __shfl_xor_sync(0x0000ffffu, v, o);
    if (t == 0) red[0] = v;
  }
  __syncthreads();
  float mean = red[0] * (1.f / 512.f);
  g_scale[t] = grn_g[t] * (gx / (mean + 1e-6f)) + 1.f;
}

// Fold: w2s[n][k] = scale[k]*w2[k][n] (bf16 split); bias2[n] = b2[n] + grn_b @ w2
__global__ __launch_bounds__(128) void k_fold(const float* __restrict__ grn_b,
                                              const float* __restrict__ w2,
                                              const float* __restrict__ b2) {
  int n = blockIdx.x;
  int t = threadIdx.x;
  float part = 0.f;
  for (int kk = t; kk < HID; kk += 128) {
    float wv = w2[kk * DIM + n];
    part += grn_b[kk] * wv;
    float sv = g_scale[kk] * wv;
    __nv_bfloat16 hi = __float2bfloat16(sv);
    g_w2s_hi[n * HID + kk] = hi;
    g_w2s_lo[n * HID + kk] = __float2bfloat16(sv - __bfloat162float(hi));
  }
  __shared__ float red[4];
#pragma unroll
  for (int o = 16; o > 0; o >>= 1) part += __shfl_xor_sync(0xffffffffu, part, o);
  if ((t & 31) == 0) red[t >> 5] = part;
  __syncthreads();
  if (t == 0) g_bias2[n] = b2[n] + red[0] + red[1] + red[2] + red[3];
}

// ---------------------------------------------------------------------------
// GEMM2: out = (h .* scale) @ w2 + bias2 + feats
// ---------------------------------------------------------------------------
__global__ __launch_bounds__(256, 1) void k_gemm2(const float* __restrict__ feats,
                                                  float* __restrict__ out) {
  extern __shared__ char smem[];
  uint32_t sb = smem_u32(smem);
  int tid = threadIdx.x, lane = tid & 31, w = tid >> 5;
  int wm = w & 1, wn = w >> 1;
  int m0 = blockIdx.x * 128;

  float acc[4][4][4] = {};
  const int CH = HID / 32;  // 16

#pragma unroll
  for (int c = 0; c < 2; c++) {
    uint32_t ssb = sb + (c % NSTAGE) * STAGE;
    ld_tile(ssb + OFF_AH, g_h_hi, m0, N_SITES, HID, c * 32, tid);
    ld_tile(ssb + OFF_AL, g_h_lo, m0, N_SITES, HID, c * 32, tid);
    ld_tile(ssb + OFF_BH, g_w2s_hi, 0, DIM, HID, c * 32, tid);
    ld_tile(ssb + OFF_BL, g_w2s_lo, 0, DIM, HID, c * 32, tid);
    CP_COMMIT();
  }
#pragma unroll 1
  for (int c = 0; c < CH; c++) {
    CP_WAIT1();
    __syncthreads();
    mma_chunk(acc, sb + (c % NSTAGE) * STAGE, wm, wn, lane);
    int pc = c + 2;
    if (pc < CH) {
      uint32_t ssb = sb + (pc % NSTAGE) * STAGE;
      ld_tile(ssb + OFF_AH, g_h_hi, m0, N_SITES, HID, pc * 32, tid);
      ld_tile(ssb + OFF_AL, g_h_lo, m0, N_SITES, HID, pc * 32, tid);
      ld_tile(ssb + OFF_BH, g_w2s_hi, 0, DIM, HID, pc * 32, tid);
      ld_tile(ssb + OFF_BL, g_w2s_lo, 0, DIM, HID, pc * 32, tid);
    }
    CP_COMMIT();
  }
  CP_WAIT0();
  __syncthreads();

  float* stg = (float*)smem;
  frag_to_stg(stg, acc, wm, wn, lane);
  __syncthreads();

  int ci = (tid & 15) * 8;
  float4 bb0 = *(const float4*)&g_bias2[ci];
  float4 bb1 = *(const float4*)&g_bias2[ci + 4];
#pragma unroll
  for (int p = 0; p < 8; p++) {
    int rr = p * 16 + (tid >> 4);
    int m = m0 + rr;
    if (m < N_SITES) {
      float4 v0 = *(float4*)&stg[rr * STG_STRIDE + ci];
      float4 v1 = *(float4*)&stg[rr * STG_STRIDE + ci + 4];
      float4 f0 = *(const float4*)&feats[(size_t)m * DIM + ci];
      float4 f1 = *(const float4*)&feats[(size_t)m * DIM + ci + 4];
      float4 o0, o1;
      o0.x = v0.x + bb0.x + f0.x; o0.y = v0.y + bb0.y + f0.y;
      o0.z = v0.z + bb0.z + f0.z; o0.w = v0.w + bb0.w + f0.w;
      o1.x = v1.x + bb1.x + f1.x; o1.y = v1.y + bb1.y + f1.y;
      o1.z = v1.z + bb1.z + f1.z; o1.w = v1.w + bb1.w + f1.w;
      *(float4*)&out[(size_t)m * DIM + ci] = o0;
      *(float4*)&out[(size_t)m * DIM + ci + 4] = o1;
    }
  }
}

// ---------------------------------------------------------------------------
extern "C" void kernel_launch(void* const* d_in, const int* in_sizes, int n_in,
                              void* d_out, int out_size) {
  const float* feats = (const float*)d_in[0];
  const int* nidx = (const int*)d_in[1];
  const float* dw_w = (const float*)d_in[2];
  const float* dw_b = (const float*)d_in[3];
  const float* ln_g = (const float*)d_in[4];
  const float* ln_b = (const float*)d_in[5];
  const float* w1 = (const float*)d_in[6];
  const float* b1 = (const float*)d_in[7];
  const float* grn_g = (const float*)d_in[8];
  const float* grn_b = (const float*)d_in[9];
  const float* w2 = (const float*)d_in[10];
  const float* b2 = (const float*)d_in[11];
  float* out = (float*)d_out;

  cudaFuncSetAttribute(k_gemm1, cudaFuncAttributeMaxDynamicSharedMemorySize, SMEM_DYN);
  cudaFuncSetAttribute(k_gemm2, cudaFuncAttributeMaxDynamicSharedMemorySize, SMEM_DYN);

  const int MT = (N_SITES + 127) / 128;  // 782
  k_prepw1<<<256, 256>>>(w1);
  k_dwln<<<N_SITES, 128>>>(feats, nidx, dw_w, dw_b, ln_g, ln_b);
  k_zero<<<1, HID>>>();
  k_gemm1<<<dim3(MT, HID / 128), 256, SMEM_DYN>>>(b1);
  k_grn<<<1, HID>>>(grn_g);
  k_fold<<<DIM, 128>>>(grn_b, w2, b2);
  k_gemm2<<<MT, 256, SMEM_DYN>>>(feats, out);
}

// round 4
// speedup vs baseline: 1.4955x; 1.0236x over previous
#include <cuda_runtime.h>
#include <cuda_bf16.h>
#include <math.h>
#include <stdint.h>

#define N_SITES 100000
#define DIM 128
#define HID 512
#define KVOL 343

// ---------------- scratch (device globals; no runtime allocation) ----------
__device__ __align__(16) __nv_bfloat16 g_x_hi[N_SITES * DIM];
__device__ __align__(16) __nv_bfloat16 g_x_lo[N_SITES * DIM];
__device__ __align__(16) __nv_bfloat16 g_h_hi[(size_t)N_SITES * HID];
__device__ __align__(16) __nv_bfloat16 g_h_lo[(size_t)N_SITES * HID];
__device__ __align__(16) __nv_bfloat16 g_w1t_hi[HID * DIM];  // [n][k]
__device__ __align__(16) __nv_bfloat16 g_w1t_lo[HID * DIM];
__device__ __align__(16) __nv_bfloat16 g_w2s_hi[DIM * HID];  // [n][k] (scaled)
__device__ __align__(16) __nv_bfloat16 g_w2s_lo[DIM * HID];
__device__ float g_sumsq[HID];
__device__ float g_scale[HID];
__device__ float g_bias2[DIM];

// ---------------- PTX helpers ----------------------------------------------
__device__ __forceinline__ uint32_t smem_u32(const void* p) {
  uint32_t a;
  asm("{ .reg .u64 t; cvta.to.shared.u64 t, %1; cvt.u32.u64 %0, t; }"
      : "=r"(a) : "l"(p));
  return a;
}

__device__ __forceinline__ void cpa16(uint32_t dst, const void* src, uint32_t sz) {
  asm volatile("cp.async.cg.shared.global [%0], [%1], 16, %2;"
               ::"r"(dst), "l"(src), "r"(sz) : "memory");
}
#define CP_COMMIT() asm volatile("cp.async.commit_group;" ::: "memory")
#define CP_WAIT1() asm volatile("cp.async.wait_group 1;" ::: "memory")
#define CP_WAIT0() asm volatile("cp.async.wait_group 0;" ::: "memory")

__device__ __forceinline__ void ldsm4(uint32_t* r, uint32_t addr) {
  asm volatile("ldmatrix.sync.aligned.m8n8.x4.shared.b16 {%0,%1,%2,%3}, [%4];"
               : "=r"(r[0]), "=r"(r[1]), "=r"(r[2]), "=r"(r[3]) : "r"(addr));
}

__device__ __forceinline__ void mma16816(float* d, const uint32_t* a, const uint32_t* b) {
  asm volatile(
      "mma.sync.aligned.m16n8k16.row.col.f32.bf16.bf16.f32 "
      "{%0,%1,%2,%3}, {%4,%5,%6,%7}, {%8,%9}, {%0,%1,%2,%3};"
      : "+f"(d[0]), "+f"(d[1]), "+f"(d[2]), "+f"(d[3])
      : "r"(a[0]), "r"(a[1]), "r"(a[2]), "r"(a[3]), "r"(b[0]), "r"(b[1]));
}

// ---------------- gemm tiling constants -------------------------------------
// Block tile 128x128, K-chunk 32, 16 warps (4 m x 4 n), warp tile 32x32.
// Stage: Ah | Al | Bh | Bl, each 128 rows x 32 bf16 (64B/row), 8KB each.
#define OFF_AH 0
#define OFF_AL 8192
#define OFF_BH 16384
#define OFF_BL 24576
#define STAGE 32768
#define NSTAGE 3
#define SMEM_DYN (NSTAGE * STAGE)  // 98304
#define STG_STRIDE 132             // fp32 epilogue stage row stride

// swizzled offset for (row, 16B-chunk c) in a 128x32 bf16 tile
__device__ __forceinline__ uint32_t swz(uint32_t r, uint32_t c) {
  return r * 64 + ((c ^ ((r >> 1) & 3)) << 4);
}

// Load one 128x32 bf16 tile (rows row0.., zero-fill past rowmax) via cp.async.
// 512 threads: exactly one 16B transfer per thread.
__device__ __forceinline__ void ld_tile(uint32_t sbase, const __nv_bfloat16* __restrict__ src,
                                        int row0, int rowmax, int ld, int k0, int tid) {
  int r = tid >> 2, c = tid & 3;
  int gr = row0 + r;
  uint32_t sz = (gr < rowmax) ? 16u : 0u;
  int grc = (gr < rowmax) ? gr : 0;
  cpa16(sbase + swz(r, c), src + (size_t)grc * ld + k0 + c * 8, sz);
}

// Compute one K=32 chunk with precomputed swizzle offsets.
// sa[mt][ks], sbo[np][ks]: per-thread ldsm offsets relative to stage base.
__device__ __forceinline__ void mma_chunk(float acc[2][4][4], uint32_t ssb,
                                          const uint32_t sa[2][2],
                                          const uint32_t sbo[2][2]) {
#pragma unroll
  for (int ks = 0; ks < 2; ks++) {
    uint32_t ah[2][4], al[2][4], bh[2][4], bl[2][4];
#pragma unroll
    for (int mt = 0; mt < 2; mt++) {
      ldsm4(ah[mt], ssb + OFF_AH + sa[mt][ks]);
      ldsm4(al[mt], ssb + OFF_AL + sa[mt][ks]);
    }
#pragma unroll
    for (int np = 0; np < 2; np++) {
      ldsm4(bh[np], ssb + OFF_BH + sbo[np][ks]);
      ldsm4(bl[np], ssb + OFF_BL + sbo[np][ks]);
    }
#pragma unroll
    for (int mt = 0; mt < 2; mt++)
#pragma unroll
      for (int nt = 0; nt < 4; nt++) {
        const uint32_t* bhp = &bh[nt >> 1][(nt & 1) * 2];
        const uint32_t* blp = &bl[nt >> 1][(nt & 1) * 2];
        mma16816(acc[mt][nt], ah[mt], bhp);
        mma16816(acc[mt][nt], al[mt], bhp);
        mma16816(acc[mt][nt], ah[mt], blp);
      }
  }
}

// Write C fragments into fp32 smem staging (row-major with pad stride).
__device__ __forceinline__ void frag_to_stg(float* stg, float acc[2][4][4],
                                            int wm, int wn, int lane) {
#pragma unroll
  for (int mt = 0; mt < 2; mt++)
#pragma unroll
    for (int nt = 0; nt < 4; nt++) {
      int m = wm * 32 + mt * 16 + (lane >> 2);
      int n = wn * 32 + nt * 8 + (lane & 3) * 2;
      *(float2*)&stg[m * STG_STRIDE + n] = make_float2(acc[mt][nt][0], acc[mt][nt][1]);
      *(float2*)&stg[(m + 8) * STG_STRIDE + n] = make_float2(acc[mt][nt][2], acc[mt][nt][3]);
    }
}

// ---------------------------------------------------------------------------
// Kernel 1: sparse depthwise conv + LayerNorm -> bf16 hi/lo split
// ---------------------------------------------------------------------------
__global__ __launch_bounds__(128) void k_dwln(
    const float* __restrict__ feats, const int* __restrict__ nidx,
    const float* __restrict__ dw_w, const float* __restrict__ dw_b,
    const float* __restrict__ ln_g, const float* __restrict__ ln_b) {
  int site = blockIdx.x;
  int tid = threadIdx.x;
  __shared__ int s_k[KVOL];
  __shared__ int s_i[KVOL];
  __shared__ int s_cnt;
  if (tid == 0) s_cnt = 0;
  __syncthreads();
  const int* row = nidx + (size_t)site * KVOL;
  for (int k = tid; k < KVOL; k += 128) {
    int idx = row[k];
    if (idx < N_SITES) {
      int p = atomicAdd(&s_cnt, 1);
      s_k[p] = k;
      s_i[p] = idx;
    }
  }
  __syncthreads();
  float acc = dw_b[tid];
  int cnt = s_cnt;
  for (int v = 0; v < cnt; v++) {
    int k = s_k[v];
    int idx = s_i[v];
    acc += __ldg(&feats[(size_t)idx * DIM + tid]) * dw_w[k * DIM + tid];
  }
  float s1 = acc, s2 = acc * acc;
#pragma unroll
  for (int o = 16; o > 0; o >>= 1) {
    s1 += __shfl_xor_sync(0xffffffffu, s1, o);
    s2 += __shfl_xor_sync(0xffffffffu, s2, o);
  }
  __shared__ float r1[4], r2[4];
  int w = tid >> 5, l = tid & 31;
  if (l == 0) { r1[w] = s1; r2[w] = s2; }
  __syncthreads();
  s1 = r1[0] + r1[1] + r1[2] + r1[3];
  s2 = r2[0] + r2[1] + r2[2] + r2[3];
  float mu = s1 * (1.f / 128.f);
  float var = s2 * (1.f / 128.f) - mu * mu;
  float rstd = rsqrtf(var + 1e-6f);
  float val = (acc - mu) * rstd * ln_g[tid] + ln_b[tid];
  __nv_bfloat16 hi = __float2bfloat16(val);
  __nv_bfloat16 lo = __float2bfloat16(val - __bfloat162float(hi));
  g_x_hi[site * DIM + tid] = hi;
  g_x_lo[site * DIM + tid] = lo;
}

__global__ void k_zero() { g_sumsq[threadIdx.x] = 0.f; }

// w1 [128,512] -> transposed split w1t [n][k]
__global__ __launch_bounds__(256) void k_prepw1(const float* __restrict__ w1) {
  int i = blockIdx.x * 256 + threadIdx.x;  // 0..65535
  int n = i >> 7, k = i & 127;
  float v = w1[k * HID + n];
  __nv_bfloat16 hi = __float2bfloat16(v);
  g_w1t_hi[i] = hi;
  g_w1t_lo[i] = __float2bfloat16(v - __bfloat162float(hi));
}

// ---------------------------------------------------------------------------
// GEMM1: h = GELU(xln @ w1 + b1)  (+ per-channel sumsq for GRN)
// ---------------------------------------------------------------------------
__global__ __launch_bounds__(512, 1) void k_gemm1(const float* __restrict__ b1) {
  extern __shared__ char smem[];
  __shared__ float s_ss[128];
  uint32_t sb = smem_u32(smem);
  int tid = threadIdx.x, lane = tid & 31, w = tid >> 5;
  int wm = w & 3, wn = w >> 2;
  int m0 = blockIdx.x * 128, n0 = blockIdx.y * 128;
  if (tid < 128) s_ss[tid] = 0.f;

  // precompute per-thread swizzled ldsm offsets
  uint32_t a_r = wm * 32 + (lane & 15);
  uint32_t a_c = (uint32_t)(lane >> 4);
  uint32_t b_r = wn * 32 + ((lane >> 4) << 3) + (lane & 7);
  uint32_t b_c = (uint32_t)((lane >> 3) & 1);
  uint32_t sa[2][2], sbo[2][2];
#pragma unroll
  for (int mt = 0; mt < 2; mt++)
#pragma unroll
    for (int ks = 0; ks < 2; ks++) sa[mt][ks] = swz(a_r + mt * 16, ks * 2 + a_c);
#pragma unroll
  for (int np = 0; np < 2; np++)
#pragma unroll
    for (int ks = 0; ks < 2; ks++) sbo[np][ks] = swz(b_r + np * 16, ks * 2 + b_c);

  float acc[2][4][4] = {};
  const int CH = DIM / 32;  // 4

#pragma unroll
  for (int c = 0; c < 2; c++) {
    uint32_t ssb = sb + (c % NSTAGE) * STAGE;
    ld_tile(ssb + OFF_AH, g_x_hi, m0, N_SITES, DIM, c * 32, tid);
    ld_tile(ssb + OFF_AL, g_x_lo, m0, N_SITES, DIM, c * 32, tid);
    ld_tile(ssb + OFF_BH, g_w1t_hi, n0, HID, DIM, c * 32, tid);
    ld_tile(ssb + OFF_BL, g_w1t_lo, n0, HID, DIM, c * 32, tid);
    CP_COMMIT();
  }
#pragma unroll 1
  for (int c = 0; c < CH; c++) {
    CP_WAIT1();
    __syncthreads();
    mma_chunk(acc, sb + (c % NSTAGE) * STAGE, sa, sbo);
    int pc = c + 2;
    if (pc < CH) {
      uint32_t ssb = sb + (pc % NSTAGE) * STAGE;
      ld_tile(ssb + OFF_AH, g_x_hi, m0, N_SITES, DIM, pc * 32, tid);
      ld_tile(ssb + OFF_AL, g_x_lo, m0, N_SITES, DIM, pc * 32, tid);
      ld_tile(ssb + OFF_BH, g_w1t_hi, n0, HID, DIM, pc * 32, tid);
      ld_tile(ssb + OFF_BL, g_w1t_lo, n0, HID, DIM, pc * 32, tid);
    }
    CP_COMMIT();
  }
  CP_WAIT0();
  __syncthreads();  // all warps done reading stages before stg overwrite

  float* stg = (float*)smem;
  frag_to_stg(stg, acc, wm, wn, lane);
  __syncthreads();

  // ---- pass 2: bias + GELU + sumsq + hi/lo store (coalesced) ---------------
  float ss[8] = {0, 0, 0, 0, 0, 0, 0, 0};
  int ci = (tid & 15) * 8;
  float4 bb0 = *(const float4*)&b1[n0 + ci];
  float4 bb1 = *(const float4*)&b1[n0 + ci + 4];
  float bias[8] = {bb0.x, bb0.y, bb0.z, bb0.w, bb1.x, bb1.y, bb1.z, bb1.w};
#pragma unroll
  for (int p = 0; p < 4; p++) {
    int rr = p * 32 + (tid >> 4);
    int m = m0 + rr;
    if (m < N_SITES) {
      float4 v0 = *(float4*)&stg[rr * STG_STRIDE + ci];
      float4 v1 = *(float4*)&stg[rr * STG_STRIDE + ci + 4];
      float v[8] = {v0.x, v0.y, v0.z, v0.w, v1.x, v1.y, v1.z, v1.w};
      union { __nv_bfloat16 b[8]; uint4 u; } uh, ul;
#pragma unroll
      for (int e = 0; e < 8; e++) {
        float x = v[e] + bias[e];
        float g = 0.5f * x * (1.f + erff(x * 0.70710678118654752f));
        ss[e] += g * g;
        uh.b[e] = __float2bfloat16(g);
        ul.b[e] = __float2bfloat16(g - __bfloat162float(uh.b[e]));
      }
      *(uint4*)&g_h_hi[(size_t)m * HID + n0 + ci] = uh.u;
      *(uint4*)&g_h_lo[(size_t)m * HID + n0 + ci] = ul.u;
    }
  }
#pragma unroll
  for (int e = 0; e < 8; e++) ss[e] += __shfl_xor_sync(0xffffffffu, ss[e], 16);
  if (lane < 16) {
#pragma unroll
    for (int e = 0; e < 8; e++) atomicAdd(&s_ss[ci + e], ss[e]);
  }
  __syncthreads();
  if (tid < 128) atomicAdd(&g_sumsq[n0 + tid], s_ss[tid]);
}

// ---------------------------------------------------------------------------
// GRN scale: scale[c] = grn_g[c] * nx[c] + 1
// ---------------------------------------------------------------------------
__global__ __launch_bounds__(512) void k_grn(const float* __restrict__ grn_g) {
  int t = threadIdx.x;
  float gx = sqrtf(g_sumsq[t]);
  __shared__ float red[16];
  float s = gx;
#pragma unroll
  for (int o = 16; o > 0; o >>= 1) s += __shfl_xor_sync(0xffffffffu, s, o);
  if ((t & 31) == 0) red[t >> 5] = s;
  __syncthreads();
  if (t < 16) {
    float v = red[t];
#pragma unroll
    for (int o = 8; o > 0; o >>= 1) v += __shfl_xor_sync(0x0000ffffu, v, o);
    if (t == 0) red[0] = v;
  }
  __syncthreads();
  float mean = red[0] * (1.f / 512.f);
  g_scale[t] = grn_g[t] * (gx / (mean + 1e-6f)) + 1.f;
}

// Fold: w2s[n][k] = scale[k]*w2[k][n] (bf16 split); bias2[n] = b2[n] + grn_b @ w2
__global__ __launch_bounds__(128) void k_fold(const float* __restrict__ grn_b,
                                              const float* __restrict__ w2,
                                              const float* __restrict__ b2) {
  int n = blockIdx.x;
  int t = threadIdx.x;
  float part = 0.f;
  for (int kk = t; kk < HID; kk += 128) {
    float wv = w2[kk * DIM + n];
    part += grn_b[kk] * wv;
    float sv = g_scale[kk] * wv;
    __nv_bfloat16 hi = __float2bfloat16(sv);
    g_w2s_hi[n * HID + kk] = hi;
    g_w2s_lo[n * HID + kk] = __float2bfloat16(sv - __bfloat162float(hi));
  }
  __shared__ float red[4];
#pragma unroll
  for (int o = 16; o > 0; o >>= 1) part += __shfl_xor_sync(0xffffffffu, part, o);
  if ((t & 31) == 0) red[t >> 5] = part;
  __syncthreads();
  if (t == 0) g_bias2[n] = b2[n] + red[0] + red[1] + red[2] + red[3];
}

// ---------------------------------------------------------------------------
// GEMM2: out = (h .* scale) @ w2 + bias2 + feats
// ---------------------------------------------------------------------------
__global__ __launch_bounds__(512, 1) void k_gemm2(const float* __restrict__ feats,
                                                  float* __restrict__ out) {
  extern __shared__ char smem[];
  uint32_t sb = smem_u32(smem);
  int tid = threadIdx.x, lane = tid & 31, w = tid >> 5;
  int wm = w & 3, wn = w >> 2;
  int m0 = blockIdx.x * 128;

  uint32_t a_r = wm * 32 + (lane & 15);
  uint32_t a_c = (uint32_t)(lane >> 4);
  uint32_t b_r = wn * 32 + ((lane >> 4) << 3) + (lane & 7);
  uint32_t b_c = (uint32_t)((lane >> 3) & 1);
  uint32_t sa[2][2], sbo[2][2];
#pragma unroll
  for (int mt = 0; mt < 2; mt++)
#pragma unroll
    for (int ks = 0; ks < 2; ks++) sa[mt][ks] = swz(a_r + mt * 16, ks * 2 + a_c);
#pragma unroll
  for (int np = 0; np < 2; np++)
#pragma unroll
    for (int ks = 0; ks < 2; ks++) sbo[np][ks] = swz(b_r + np * 16, ks * 2 + b_c);

  float acc[2][4][4] = {};
  const int CH = HID / 32;  // 16

#pragma unroll
  for (int c = 0; c < 2; c++) {
    uint32_t ssb = sb + (c % NSTAGE) * STAGE;
    ld_tile(ssb + OFF_AH, g_h_hi, m0, N_SITES, HID, c * 32, tid);
    ld_tile(ssb + OFF_AL, g_h_lo, m0, N_SITES, HID, c * 32, tid);
    ld_tile(ssb + OFF_BH, g_w2s_hi, 0, DIM, HID, c * 32, tid);
    ld_tile(ssb + OFF_BL, g_w2s_lo, 0, DIM, HID, c * 32, tid);
    CP_COMMIT();
  }
#pragma unroll 1
  for (int c = 0; c < CH; c++) {
    CP_WAIT1();
    __syncthreads();
    mma_chunk(acc, sb + (c % NSTAGE) * STAGE, sa, sbo);
    int pc = c + 2;
    if (pc < CH) {
      uint32_t ssb = sb + (pc % NSTAGE) * STAGE;
      ld_tile(ssb + OFF_AH, g_h_hi, m0, N_SITES, HID, pc * 32, tid);
      ld_tile(ssb + OFF_AL, g_h_lo, m0, N_SITES, HID, pc * 32, tid);
      ld_tile(ssb + OFF_BH, g_w2s_hi, 0, DIM, HID, pc * 32, tid);
      ld_tile(ssb + OFF_BL, g_w2s_lo, 0, DIM, HID, pc * 32, tid);
    }
    CP_COMMIT();
  }
  CP_WAIT0();
  __syncthreads();

  float* stg = (float*)smem;
  frag_to_stg(stg, acc, wm, wn, lane);
  __syncthreads();

  int ci = (tid & 15) * 8;
  float4 bb0 = *(const float4*)&g_bias2[ci];
  float4 bb1 = *(const float4*)&g_bias2[ci + 4];
#pragma unroll
  for (int p = 0; p < 4; p++) {
    int rr = p * 32 + (tid >> 4);
    int m = m0 + rr;
    if (m < N_SITES) {
      float4 v0 = *(float4*)&stg[rr * STG_STRIDE + ci];
      float4 v1 = *(float4*)&stg[rr * STG_STRIDE + ci + 4];
      float4 f0 = *(const float4*)&feats[(size_t)m * DIM + ci];
      float4 f1 = *(const float4*)&feats[(size_t)m * DIM + ci + 4];
      float4 o0, o1;
      o0.x = v0.x + bb0.x + f0.x; o0.y = v0.y + bb0.y + f0.y;
      o0.z = v0.z + bb0.z + f0.z; o0.w = v0.w + bb0.w + f0.w;
      o1.x = v1.x + bb1.x + f1.x; o1.y = v1.y + bb1.y + f1.y;
      o1.z = v1.z + bb1.z + f1.z; o1.w = v1.w + bb1.w + f1.w;
      *(float4*)&out[(size_t)m * DIM + ci] = o0;
      *(float4*)&out[(size_t)m * DIM + ci + 4] = o1;
    }
  }
}

// ---------------------------------------------------------------------------
extern "C" void kernel_launch(void* const* d_in, const int* in_sizes, int n_in,
                              void* d_out, int out_size) {
  const float* feats = (const float*)d_in[0];
  const int* nidx = (const int*)d_in[1];
  const float* dw_w = (const float*)d_in[2];
  const float* dw_b = (const float*)d_in[3];
  const float* ln_g = (const float*)d_in[4];
  const float* ln_b = (const float*)d_in[5];
  const float* w1 = (const float*)d_in[6];
  const float* b1 = (const float*)d_in[7];
  const float* grn_g = (const float*)d_in[8];
  const float* grn_b = (const float*)d_in[9];
  const float* w2 = (const float*)d_in[10];
  const float* b2 = (const float*)d_in[11];
  float* out = (float*)d_out;

  cudaFuncSetAttribute(k_gemm1, cudaFuncAttributeMaxDynamicSharedMemorySize, SMEM_DYN);
  cudaFuncSetAttribute(k_gemm2, cudaFuncAttributeMaxDynamicSharedMemorySize, SMEM_DYN);

  const int MT = (N_SITES + 127) / 128;  // 782
  k_prepw1<<<256, 256>>>(w1);
  k_dwln<<<N_SITES, 128>>>(feats, nidx, dw_w, dw_b, ln_g, ln_b);
  k_zero<<<1, HID>>>();
  k_gemm1<<<dim3(MT, HID / 128), 512, SMEM_DYN>>>(b1);
  k_grn<<<1, HID>>>(grn_g);
  k_fold<<<DIM, 128>>>(grn_b, w2, b2);
  k_gemm2<<<MT, 512, SMEM_DYN>>>(feats, out);
}

// round 5
// speedup vs baseline: 1.7839x; 1.1928x over previous
#include <cuda_runtime.h>
#include <cuda_bf16.h>
#include <math.h>
#include <stdint.h>

#define N_SITES 100000
#define DIM 128
#define HID 512
#define KVOL 343

// ---------------- scratch (device globals; no runtime allocation) ----------
__device__ __align__(16) __nv_bfloat16 g_x_hi[N_SITES * DIM];
__device__ __align__(16) __nv_bfloat16 g_x_lo[N_SITES * DIM];
__device__ __align__(16) __nv_bfloat16 g_h_hi[(size_t)N_SITES * HID];
__device__ __align__(16) __nv_bfloat16 g_h_lo[(size_t)N_SITES * HID];
__device__ __align__(16) __nv_bfloat16 g_w1t_hi[HID * DIM];  // [n][k]
__device__ __align__(16) __nv_bfloat16 g_w1t_lo[HID * DIM];
__device__ __align__(16) __nv_bfloat16 g_w2s_hi[DIM * HID];  // [n][k] (scaled)
__device__ __align__(16) __nv_bfloat16 g_w2s_lo[DIM * HID];
__device__ float g_sumsq[HID];
__device__ float g_scale[HID];
__device__ float g_bias2[DIM];

// ---------------- PTX helpers ----------------------------------------------
__device__ __forceinline__ uint32_t smem_u32(const void* p) {
  uint32_t a;
  asm("{ .reg .u64 t; cvta.to.shared.u64 t, %1; cvt.u32.u64 %0, t; }"
      : "=r"(a) : "l"(p));
  return a;
}

__device__ __forceinline__ void cpa16(uint32_t dst, const void* src, uint32_t sz) {
  asm volatile("cp.async.cg.shared.global [%0], [%1], 16, %2;"
               ::"r"(dst), "l"(src), "r"(sz) : "memory");
}
#define CP_COMMIT() asm volatile("cp.async.commit_group;" ::: "memory")
#define CP_WAIT1() asm volatile("cp.async.wait_group 1;" ::: "memory")
#define CP_WAIT0() asm volatile("cp.async.wait_group 0;" ::: "memory")

__device__ __forceinline__ void ldsm4(uint32_t* r, uint32_t addr) {
  asm volatile("ldmatrix.sync.aligned.m8n8.x4.shared.b16 {%0,%1,%2,%3}, [%4];"
               : "=r"(r[0]), "=r"(r[1]), "=r"(r[2]), "=r"(r[3]) : "r"(addr));
}

__device__ __forceinline__ void mma16816(float* d, const uint32_t* a, const uint32_t* b) {
  asm volatile(
      "mma.sync.aligned.m16n8k16.row.col.f32.bf16.bf16.f32 "
      "{%0,%1,%2,%3}, {%4,%5,%6,%7}, {%8,%9}, {%0,%1,%2,%3};"
      : "+f"(d[0]), "+f"(d[1]), "+f"(d[2]), "+f"(d[3])
      : "r"(a[0]), "r"(a[1]), "r"(a[2]), "r"(a[3]), "r"(b[0]), "r"(b[1]));
}

// ---------------- gemm tiling constants -------------------------------------
// Block tile 128x128, K-chunk 32, 8 warps (2 m x 4 n), warp tile 64x32.
// Stage: Ah | Al | Bh | Bl, each 128 rows x 32 bf16 (64B/row), 8KB each.
#define OFF_AH 0
#define OFF_AL 8192
#define OFF_BH 16384
#define OFF_BL 24576
#define STAGE 32768
#define NSTAGE 3
#define SMEM_DYN (NSTAGE * STAGE)  // 98304
#define STG_STRIDE 132             // fp32 epilogue stage row stride

// swizzled offset for (row, 16B-chunk c) in a 128x32 bf16 tile
__device__ __forceinline__ uint32_t swz(uint32_t r, uint32_t c) {
  return r * 64 + ((c ^ ((r >> 1) & 3)) << 4);
}

// Load one 128x32 bf16 tile (rows row0.., zero-fill past rowmax) via cp.async.
// 256 threads: two 16B transfers per thread.
__device__ __forceinline__ void ld_tile(uint32_t sbase, const __nv_bfloat16* __restrict__ src,
                                        int row0, int rowmax, int ld, int k0, int tid) {
#pragma unroll
  for (int i = 0; i < 2; i++) {
    int g = i * 256 + tid;
    int r = g >> 2, c = g & 3;
    int gr = row0 + r;
    uint32_t sz = (gr < rowmax) ? 16u : 0u;
    int grc = (gr < rowmax) ? gr : 0;
    cpa16(sbase + swz(r, c), src + (size_t)grc * ld + k0 + c * 8, sz);
  }
}

// Compute one K=32 chunk with precomputed swizzle offsets.
// B fragments loaded once per k-step; A hi/lo per m-tile (register pressure).
__device__ __forceinline__ void mma_chunk(float acc[4][4][4], uint32_t ssb,
                                          const uint32_t sa[4][2],
                                          const uint32_t sbo[2][2]) {
#pragma unroll
  for (int ks = 0; ks < 2; ks++) {
    uint32_t bh[2][4], bl[2][4];
#pragma unroll
    for (int np = 0; np < 2; np++) {
      ldsm4(bh[np], ssb + OFF_BH + sbo[np][ks]);
      ldsm4(bl[np], ssb + OFF_BL + sbo[np][ks]);
    }
#pragma unroll
    for (int mt = 0; mt < 4; mt++) {
      uint32_t ah[4], al[4];
      ldsm4(ah, ssb + OFF_AH + sa[mt][ks]);
      ldsm4(al, ssb + OFF_AL + sa[mt][ks]);
#pragma unroll
      for (int nt = 0; nt < 4; nt++) {
        const uint32_t* bhp = &bh[nt >> 1][(nt & 1) * 2];
        const uint32_t* blp = &bl[nt >> 1][(nt & 1) * 2];
        mma16816(acc[mt][nt], ah, bhp);
        mma16816(acc[mt][nt], al, bhp);
        mma16816(acc[mt][nt], ah, blp);
      }
    }
  }
}

// Write C fragments into fp32 smem staging (row-major with pad stride).
__device__ __forceinline__ void frag_to_stg(float* stg, float acc[4][4][4],
                                            int wm, int wn, int lane) {
#pragma unroll
  for (int mt = 0; mt < 4; mt++)
#pragma unroll
    for (int nt = 0; nt < 4; nt++) {
      int m = wm * 64 + mt * 16 + (lane >> 2);
      int n = wn * 32 + nt * 8 + (lane & 3) * 2;
      *(float2*)&stg[m * STG_STRIDE + n] = make_float2(acc[mt][nt][0], acc[mt][nt][1]);
      *(float2*)&stg[(m + 8) * STG_STRIDE + n] = make_float2(acc[mt][nt][2], acc[mt][nt][3]);
    }
}

// ---------------------------------------------------------------------------
// Kernel 1: sparse depthwise conv + LayerNorm -> bf16 hi/lo split
// ---------------------------------------------------------------------------
__global__ __launch_bounds__(128) void k_dwln(
    const float* __restrict__ feats, const int* __restrict__ nidx,
    const float* __restrict__ dw_w, const float* __restrict__ dw_b,
    const float* __restrict__ ln_g, const float* __restrict__ ln_b) {
  int site = blockIdx.x;
  int tid = threadIdx.x;
  __shared__ int s_k[KVOL];
  __shared__ int s_i[KVOL];
  __shared__ int s_cnt;
  if (tid == 0) s_cnt = 0;
  __syncthreads();
  const int* row = nidx + (size_t)site * KVOL;
  for (int k = tid; k < KVOL; k += 128) {
    int idx = row[k];
    if (idx < N_SITES) {
      int p = atomicAdd(&s_cnt, 1);
      s_k[p] = k;
      s_i[p] = idx;
    }
  }
  __syncthreads();
  float acc = dw_b[tid];
  int cnt = s_cnt;
  for (int v = 0; v < cnt; v++) {
    int k = s_k[v];
    int idx = s_i[v];
    acc += __ldg(&feats[(size_t)idx * DIM + tid]) * dw_w[k * DIM + tid];
  }
  float s1 = acc, s2 = acc * acc;
#pragma unroll
  for (int o = 16; o > 0; o >>= 1) {
    s1 += __shfl_xor_sync(0xffffffffu, s1, o);
    s2 += __shfl_xor_sync(0xffffffffu, s2, o);
  }
  __shared__ float r1[4], r2[4];
  int w = tid >> 5, l = tid & 31;
  if (l == 0) { r1[w] = s1; r2[w] = s2; }
  __syncthreads();
  s1 = r1[0] + r1[1] + r1[2] + r1[3];
  s2 = r2[0] + r2[1] + r2[2] + r2[3];
  float mu = s1 * (1.f / 128.f);
  float var = s2 * (1.f / 128.f) - mu * mu;
  float rstd = rsqrtf(var + 1e-6f);
  float val = (acc - mu) * rstd * ln_g[tid] + ln_b[tid];
  __nv_bfloat16 hi = __float2bfloat16(val);
  __nv_bfloat16 lo = __float2bfloat16(val - __bfloat162float(hi));
  g_x_hi[site * DIM + tid] = hi;
  g_x_lo[site * DIM + tid] = lo;
}

__global__ void k_zero() { g_sumsq[threadIdx.x] = 0.f; }

// w1 [128,512] -> transposed split w1t [n][k]
__global__ __launch_bounds__(256) void k_prepw1(const float* __restrict__ w1) {
  int i = blockIdx.x * 256 + threadIdx.x;  // 0..65535
  int n = i >> 7, k = i & 127;
  float v = w1[k * HID + n];
  __nv_bfloat16 hi = __float2bfloat16(v);
  g_w1t_hi[i] = hi;
  g_w1t_lo[i] = __float2bfloat16(v - __bfloat162float(hi));
}

// ---------------------------------------------------------------------------
// GEMM1: h = GELU(xln @ w1 + b1)  (+ per-channel sumsq for GRN)
// 256 threads, 2 CTAs/SM (regs capped at 128 via launch_bounds).
// ---------------------------------------------------------------------------
__global__ __launch_bounds__(256, 2) void k_gemm1(const float* __restrict__ b1) {
  extern __shared__ char smem[];
  __shared__ float s_ss[128];
  uint32_t sb = smem_u32(smem);
  int tid = threadIdx.x, lane = tid & 31, w = tid >> 5;
  int wm = w & 1, wn = w >> 1;
  int m0 = blockIdx.x * 128, n0 = blockIdx.y * 128;
  if (tid < 128) s_ss[tid] = 0.f;

  // precompute per-thread swizzled ldsm offsets
  uint32_t a_r = wm * 64 + (lane & 15);
  uint32_t a_c = (uint32_t)(lane >> 4);
  uint32_t b_r = wn * 32 + ((lane >> 4) << 3) + (lane & 7);
  uint32_t b_c = (uint32_t)((lane >> 3) & 1);
  uint32_t sa[4][2], sbo[2][2];
#pragma unroll
  for (int mt = 0; mt < 4; mt++)
#pragma unroll
    for (int ks = 0; ks < 2; ks++) sa[mt][ks] = swz(a_r + mt * 16, ks * 2 + a_c);
#pragma unroll
  for (int np = 0; np < 2; np++)
#pragma unroll
    for (int ks = 0; ks < 2; ks++) sbo[np][ks] = swz(b_r + np * 16, ks * 2 + b_c);

  float acc[4][4][4] = {};
  const int CH = DIM / 32;  // 4

#pragma unroll
  for (int c = 0; c < 2; c++) {
    uint32_t ssb = sb + (c % NSTAGE) * STAGE;
    ld_tile(ssb + OFF_AH, g_x_hi, m0, N_SITES, DIM, c * 32, tid);
    ld_tile(ssb + OFF_AL, g_x_lo, m0, N_SITES, DIM, c * 32, tid);
    ld_tile(ssb + OFF_BH, g_w1t_hi, n0, HID, DIM, c * 32, tid);
    ld_tile(ssb + OFF_BL, g_w1t_lo, n0, HID, DIM, c * 32, tid);
    CP_COMMIT();
  }
#pragma unroll 1
  for (int c = 0; c < CH; c++) {
    CP_WAIT1();
    __syncthreads();
    mma_chunk(acc, sb + (c % NSTAGE) * STAGE, sa, sbo);
    int pc = c + 2;
    if (pc < CH) {
      uint32_t ssb = sb + (pc % NSTAGE) * STAGE;
      ld_tile(ssb + OFF_AH, g_x_hi, m0, N_SITES, DIM, pc * 32, tid);
      ld_tile(ssb + OFF_AL, g_x_lo, m0, N_SITES, DIM, pc * 32, tid);
      ld_tile(ssb + OFF_BH, g_w1t_hi, n0, HID, DIM, pc * 32, tid);
      ld_tile(ssb + OFF_BL, g_w1t_lo, n0, HID, DIM, pc * 32, tid);
    }
    CP_COMMIT();
  }
  CP_WAIT0();
  __syncthreads();  // all warps done reading stages before stg overwrite

  float* stg = (float*)smem;
  frag_to_stg(stg, acc, wm, wn, lane);
  __syncthreads();

  // ---- pass 2: bias + GELU + sumsq + hi/lo store (coalesced) ---------------
  float ss[8] = {0, 0, 0, 0, 0, 0, 0, 0};
  int ci = (tid & 15) * 8;
  float4 bb0 = *(const float4*)&b1[n0 + ci];
  float4 bb1 = *(const float4*)&b1[n0 + ci + 4];
  float bias[8] = {bb0.x, bb0.y, bb0.z, bb0.w, bb1.x, bb1.y, bb1.z, bb1.w};
#pragma unroll
  for (int p = 0; p < 8; p++) {
    int rr = p * 16 + (tid >> 4);
    int m = m0 + rr;
    if (m < N_SITES) {
      float4 v0 = *(float4*)&stg[rr * STG_STRIDE + ci];
      float4 v1 = *(float4*)&stg[rr * STG_STRIDE + ci + 4];
      float v[8] = {v0.x, v0.y, v0.z, v0.w, v1.x, v1.y, v1.z, v1.w};
      union { __nv_bfloat16 b[8]; uint4 u; } uh, ul;
#pragma unroll
      for (int e = 0; e < 8; e++) {
        float x = v[e] + bias[e];
        float g = 0.5f * x * (1.f + erff(x * 0.70710678118654752f));
        ss[e] += g * g;
        uh.b[e] = __float2bfloat16(g);
        ul.b[e] = __float2bfloat16(g - __bfloat162float(uh.b[e]));
      }
      *(uint4*)&g_h_hi[(size_t)m * HID + n0 + ci] = uh.u;
      *(uint4*)&g_h_lo[(size_t)m * HID + n0 + ci] = ul.u;
    }
  }
#pragma unroll
  for (int e = 0; e < 8; e++) ss[e] += __shfl_xor_sync(0xffffffffu, ss[e], 16);
  if (lane < 16) {
#pragma unroll
    for (int e = 0; e < 8; e++) atomicAdd(&s_ss[ci + e], ss[e]);
  }
  __syncthreads();
  if (tid < 128) atomicAdd(&g_sumsq[n0 + tid], s_ss[tid]);
}

// ---------------------------------------------------------------------------
// GRN scale: scale[c] = grn_g[c] * nx[c] + 1
// ---------------------------------------------------------------------------
__global__ __launch_bounds__(512) void k_grn(const float* __restrict__ grn_g) {
  int t = threadIdx.x;
  float gx = sqrtf(g_sumsq[t]);
  __shared__ float red[16];
  float s = gx;
#pragma unroll
  for (int o = 16; o > 0; o >>= 1) s += __shfl_xor_sync(0xffffffffu, s, o);
  if ((t & 31) == 0) red[t >> 5] = s;
  __syncthreads();
  if (t < 16) {
    float v = red[t];
#pragma unroll
    for (int o = 8; o > 0; o >>= 1) v += __shfl_xor_sync(0x0000ffffu, v, o);
    if (t == 0) red[0] = v;
  }
  __syncthreads();
  float mean = red[0] * (1.f / 512.f);
  g_scale[t] = grn_g[t] * (gx / (mean + 1e-6f)) + 1.f;
}

// Fold: w2s[n][k] = scale[k]*w2[k][n] (bf16 split); bias2[n] = b2[n] + grn_b @ w2
__global__ __launch_bounds__(128) void k_fold(const float* __restrict__ grn_b,
                                              const float* __restrict__ w2,
                                              const float* __restrict__ b2) {
  int n = blockIdx.x;
  int t = threadIdx.x;
  float part = 0.f;
  for (int kk = t; kk < HID; kk += 128) {
    float wv = w2[kk * DIM + n];
    part += grn_b[kk] * wv;
    float sv = g_scale[kk] * wv;
    __nv_bfloat16 hi = __float2bfloat16(sv);
    g_w2s_hi[n * HID + kk] = hi;
    g_w2s_lo[n * HID + kk] = __float2bfloat16(sv - __bfloat162float(hi));
  }
  __shared__ float red[4];
#pragma unroll
  for (int o = 16; o > 0; o >>= 1) part += __shfl_xor_sync(0xffffffffu, part, o);
  if ((t & 31) == 0) red[t >> 5] = part;
  __syncthreads();
  if (t == 0) g_bias2[n] = b2[n] + red[0] + red[1] + red[2] + red[3];
}

// ---------------------------------------------------------------------------
// GEMM2: out = (h .* scale) @ w2 + bias2 + feats
// ---------------------------------------------------------------------------
__global__ __launch_bounds__(256, 2) void k_gemm2(const float* __restrict__ feats,
                                                  float* __restrict__ out) {
  extern __shared__ char smem[];
  uint32_t sb = smem_u32(smem);
  int tid = threadIdx.x, lane = tid & 31, w = tid >> 5;
  int wm = w & 1, wn = w >> 1;
  int m0 = blockIdx.x * 128;

  uint32_t a_r = wm * 64 + (lane & 15);
  uint32_t a_c = (uint32_t)(lane >> 4);
  uint32_t b_r = wn * 32 + ((lane >> 4) << 3) + (lane & 7);
  uint32_t b_c = (uint32_t)((lane >> 3) & 1);
  uint32_t sa[4][2], sbo[2][2];
#pragma unroll
  for (int mt = 0; mt < 4; mt++)
#pragma unroll
    for (int ks = 0; ks < 2; ks++) sa[mt][ks] = swz(a_r + mt * 16, ks * 2 + a_c);
#pragma unroll
  for (int np = 0; np < 2; np++)
#pragma unroll
    for (int ks = 0; ks < 2; ks++) sbo[np][ks] = swz(b_r + np * 16, ks * 2 + b_c);

  float acc[4][4][4] = {};
  const int CH = HID / 32;  // 16

#pragma unroll
  for (int c = 0; c < 2; c++) {
    uint32_t ssb = sb + (c % NSTAGE) * STAGE;
    ld_tile(ssb + OFF_AH, g_h_hi, m0, N_SITES, HID, c * 32, tid);
    ld_tile(ssb + OFF_AL, g_h_lo, m0, N_SITES, HID, c * 32, tid);
    ld_tile(ssb + OFF_BH, g_w2s_hi, 0, DIM, HID, c * 32, tid);
    ld_tile(ssb + OFF_BL, g_w2s_lo, 0, DIM, HID, c * 32, tid);
    CP_COMMIT();
  }
#pragma unroll 1
  for (int c = 0; c < CH; c++) {
    CP_WAIT1();
    __syncthreads();
    mma_chunk(acc, sb + (c % NSTAGE) * STAGE, sa, sbo);
    int pc = c + 2;
    if (pc < CH) {
      uint32_t ssb = sb + (pc % NSTAGE) * STAGE;
      ld_tile(ssb + OFF_AH, g_h_hi, m0, N_SITES, HID, pc * 32, tid);
      ld_tile(ssb + OFF_AL, g_h_lo, m0, N_SITES, HID, pc * 32, tid);
      ld_tile(ssb + OFF_BH, g_w2s_hi, 0, DIM, HID, pc * 32, tid);
      ld_tile(ssb + OFF_BL, g_w2s_lo, 0, DIM, HID, pc * 32, tid);
    }
    CP_COMMIT();
  }
  CP_WAIT0();
  __syncthreads();

  float* stg = (float*)smem;
  frag_to_stg(stg, acc, wm, wn, lane);
  __syncthreads();

  int ci = (tid & 15) * 8;
  float4 bb0 = *(const float4*)&g_bias2[ci];
  float4 bb1 = *(const float4*)&g_bias2[ci + 4];
#pragma unroll
  for (int p = 0; p < 8; p++) {
    int rr = p * 16 + (tid >> 4);
    int m = m0 + rr;
    if (m < N_SITES) {
      float4 v0 = *(float4*)&stg[rr * STG_STRIDE + ci];
      float4 v1 = *(float4*)&stg[rr * STG_STRIDE + ci + 4];
      float4 f0 = *(const float4*)&feats[(size_t)m * DIM + ci];
      float4 f1 = *(const float4*)&feats[(size_t)m * DIM + ci + 4];
      float4 o0, o1;
      o0.x = v0.x + bb0.x + f0.x; o0.y = v0.y + bb0.y + f0.y;
      o0.z = v0.z + bb0.z + f0.z; o0.w = v0.w + bb0.w + f0.w;
      o1.x = v1.x + bb1.x + f1.x; o1.y = v1.y + bb1.y + f1.y;
      o1.z = v1.z + bb1.z + f1.z; o1.w = v1.w + bb1.w + f1.w;
      *(float4*)&out[(size_t)m * DIM + ci] = o0;
      *(float4*)&out[(size_t)m * DIM + ci + 4] = o1;
    }
  }
}

// ---------------------------------------------------------------------------
extern "C" void kernel_launch(void* const* d_in, const int* in_sizes, int n_in,
                              void* d_out, int out_size) {
  const float* feats = (const float*)d_in[0];
  const int* nidx = (const int*)d_in[1];
  const float* dw_w = (const float*)d_in[2];
  const float* dw_b = (const float*)d_in[3];
  const float* ln_g = (const float*)d_in[4];
  const float* ln_b = (const float*)d_in[5];
  const float* w1 = (const float*)d_in[6];
  const float* b1 = (const float*)d_in[7];
  const float* grn_g = (const float*)d_in[8];
  const float* grn_b = (const float*)d_in[9];
  const float* w2 = (const float*)d_in[10];
  const float* b2 = (const float*)d_in[11];
  float* out = (float*)d_out;

  cudaFuncSetAttribute(k_gemm1, cudaFuncAttributeMaxDynamicSharedMemorySize, SMEM_DYN);
  cudaFuncSetAttribute(k_gemm2, cudaFuncAttributeMaxDynamicSharedMemorySize, SMEM_DYN);

  const int MT = (N_SITES + 127) / 128;  // 782
  k_prepw1<<<256, 256>>>(w1);
  k_dwln<<<N_SITES, 128>>>(feats, nidx, dw_w, dw_b, ln_g, ln_b);
  k_zero<<<1, HID>>>();
  k_gemm1<<<dim3(MT, HID / 128), 256, SMEM_DYN>>>(b1);
  k_grn<<<1, HID>>>(grn_g);
  k_fold<<<DIM, 128>>>(grn_b, w2, b2);
  k_gemm2<<<MT, 256, SMEM_DYN>>>(feats, out);
}

// round 6
// speedup vs baseline: 2.3604x; 1.3232x over previous
#include <cuda_runtime.h>
#include <cuda_fp16.h>
#include <math.h>
#include <stdint.h>

#define N_SITES 100000
#define DIM 128
#define HID 512
#define KVOL 343

// ---------------- scratch (device globals; no runtime allocation) ----------
__device__ __align__(16) __half g_x[N_SITES * DIM];            // LN output
__device__ __align__(16) __half g_h[(size_t)N_SITES * HID];    // GELU output
__device__ __align__(16) __half g_w1t[HID * DIM];              // w1 transposed [n][k]
__device__ __align__(16) __half g_w2s[DIM * HID];              // scaled w2 [n][k]
__device__ float g_sumsq[HID];
__device__ float g_scale[HID];
__device__ float g_bias2[DIM];

// ---------------- PTX helpers ----------------------------------------------
__device__ __forceinline__ uint32_t smem_u32(const void* p) {
  uint32_t a;
  asm("{ .reg .u64 t; cvta.to.shared.u64 t, %1; cvt.u32.u64 %0, t; }"
      : "=r"(a) : "l"(p));
  return a;
}

__device__ __forceinline__ void cpa16(uint32_t dst, const void* src, uint32_t sz) {
  asm volatile("cp.async.cg.shared.global [%0], [%1], 16, %2;"
               ::"r"(dst), "l"(src), "r"(sz) : "memory");
}
#define CP_COMMIT() asm volatile("cp.async.commit_group;" ::: "memory")
#define CP_WAIT1() asm volatile("cp.async.wait_group 1;" ::: "memory")
#define CP_WAIT0() asm volatile("cp.async.wait_group 0;" ::: "memory")

__device__ __forceinline__ void ldsm4(uint32_t* r, uint32_t addr) {
  asm volatile("ldmatrix.sync.aligned.m8n8.x4.shared.b16 {%0,%1,%2,%3}, [%4];"
               : "=r"(r[0]), "=r"(r[1]), "=r"(r[2]), "=r"(r[3]) : "r"(addr));
}

__device__ __forceinline__ void mma16816(float* d, const uint32_t* a, const uint32_t* b) {
  asm volatile(
      "mma.sync.aligned.m16n8k16.row.col.f32.f16.f16.f32 "
      "{%0,%1,%2,%3}, {%4,%5,%6,%7}, {%8,%9}, {%0,%1,%2,%3};"
      : "+f"(d[0]), "+f"(d[1]), "+f"(d[2]), "+f"(d[3])
      : "r"(a[0]), "r"(a[1]), "r"(a[2]), "r"(a[3]), "r"(b[0]), "r"(b[1]));
}

// ---------------- tiling ----------------------------------------------------
// fp16 tiles, rows of 64 cols = 128B = 8 x 16B chunks, XOR-8 swizzle.
// Block tile 128x128, 8 warps (2m x 4n), warp tile 64x32.
#define STG_STRIDE 132
#define G1_OFF_B 32768
#define G1_SMEM 67584   // max(64KB tiles, 128*132*4 stg)
#define G2_STAGE 32768  // A 16KB + B 16KB
#define G2_OFF_B 16384
#define G2_SMEM 98304   // 3 stages (stg 67.5KB reuses)

// Write C fragments into fp32 smem staging (row-major, padded stride).
__device__ __forceinline__ void frag_to_stg(float* stg, float acc[4][4][4],
                                            int wm, int wn, int lane) {
#pragma unroll
  for (int mt = 0; mt < 4; mt++)
#pragma unroll
    for (int nt = 0; nt < 4; nt++) {
      int m = wm * 64 + mt * 16 + (lane >> 2);
      int n = wn * 32 + nt * 8 + (lane & 3) * 2;
      *(float2*)&stg[m * STG_STRIDE + n] = make_float2(acc[mt][nt][0], acc[mt][nt][1]);
      *(float2*)&stg[(m + 8) * STG_STRIDE + n] = make_float2(acc[mt][nt][2], acc[mt][nt][3]);
    }
}

// ---------------------------------------------------------------------------
// Kernel 1: sparse depthwise conv + LayerNorm -> fp16
// ---------------------------------------------------------------------------
__global__ __launch_bounds__(128) void k_dwln(
    const float* __restrict__ feats, const int* __restrict__ nidx,
    const float* __restrict__ dw_w, const float* __restrict__ dw_b,
    const float* __restrict__ ln_g, const float* __restrict__ ln_b) {
  int site = blockIdx.x;
  int tid = threadIdx.x;
  __shared__ int s_k[KVOL];
  __shared__ int s_i[KVOL];
  __shared__ int s_cnt;
  if (tid == 0) s_cnt = 0;
  __syncthreads();
  const int* row = nidx + (size_t)site * KVOL;
  for (int k = tid; k < KVOL; k += 128) {
    int idx = row[k];
    if (idx < N_SITES) {
      int p = atomicAdd(&s_cnt, 1);
      s_k[p] = k;
      s_i[p] = idx;
    }
  }
  __syncthreads();
  float acc = dw_b[tid];
  int cnt = s_cnt;
  for (int v = 0; v < cnt; v++) {
    int k = s_k[v];
    int idx = s_i[v];
    acc += __ldg(&feats[(size_t)idx * DIM + tid]) * dw_w[k * DIM + tid];
  }
  float s1 = acc, s2 = acc * acc;
#pragma unroll
  for (int o = 16; o > 0; o >>= 1) {
    s1 += __shfl_xor_sync(0xffffffffu, s1, o);
    s2 += __shfl_xor_sync(0xffffffffu, s2, o);
  }
  __shared__ float r1[4], r2[4];
  int w = tid >> 5, l = tid & 31;
  if (l == 0) { r1[w] = s1; r2[w] = s2; }
  __syncthreads();
  s1 = r1[0] + r1[1] + r1[2] + r1[3];
  s2 = r2[0] + r2[1] + r2[2] + r2[3];
  float mu = s1 * (1.f / 128.f);
  float var = s2 * (1.f / 128.f) - mu * mu;
  float rstd = rsqrtf(var + 1e-6f);
  float val = (acc - mu) * rstd * ln_g[tid] + ln_b[tid];
  g_x[site * DIM + tid] = __float2half_rn(val);
}

__global__ void k_zero() { g_sumsq[threadIdx.x] = 0.f; }

// w1 [128,512] -> transposed fp16 w1t [n][k]
__global__ __launch_bounds__(256) void k_prepw1(const float* __restrict__ w1) {
  int i = blockIdx.x * 256 + threadIdx.x;  // 0..65535
  int n = i >> 7, k = i & 127;
  g_w1t[i] = __float2half_rn(w1[k * HID + n]);
}

// ---------------------------------------------------------------------------
// GEMM1: h = GELU(x @ w1 + b1)  (+ per-channel sumsq for GRN)
// Monolithic K=128: one 64KB load, one sync, 8 k-steps, fused epilogue.
// ---------------------------------------------------------------------------
__global__ __launch_bounds__(256, 2) void k_gemm1(const float* __restrict__ b1) {
  extern __shared__ char smem[];
  __shared__ float s_ss[128];
  uint32_t sb = smem_u32(smem);
  int tid = threadIdx.x, lane = tid & 31, w = tid >> 5;
  int wm = w & 1, wn = w >> 1;
  int m0 = blockIdx.x * 128, n0 = blockIdx.y * 128;
  if (tid < 128) s_ss[tid] = 0.f;

  // ---- load A (x[m0..], 128x128 fp16) and B (w1t[n0..]) ----
#pragma unroll
  for (int i = 0; i < 8; i++) {
    int g = i * 256 + tid;
    int r = g >> 4, c16 = g & 15;
    uint32_t dst = sb + ((uint32_t)(c16 >> 3) << 14) + r * 128 + (((c16 & 7) ^ (r & 7)) << 4);
    int gr = m0 + r;
    uint32_t sz = (gr < N_SITES) ? 16u : 0u;
    int grc = (gr < N_SITES) ? gr : 0;
    cpa16(dst, g_x + (size_t)grc * DIM + c16 * 8, sz);
  }
#pragma unroll
  for (int i = 0; i < 8; i++) {
    int g = i * 256 + tid;
    int r = g >> 4, c16 = g & 15;
    uint32_t dst = sb + G1_OFF_B + ((uint32_t)(c16 >> 3) << 14) + r * 128 +
                   (((c16 & 7) ^ (r & 7)) << 4);
    cpa16(dst, g_w1t + (size_t)(n0 + r) * DIM + c16 * 8, 16);
  }
  CP_COMMIT();

  // ---- ldsm offset precompute ----
  uint32_t abase[4], axor[4], bbase[2], bxor[2];
  {
    int ar = wm * 64 + (lane & 15);
#pragma unroll
    for (int mt = 0; mt < 4; mt++) {
      int r = ar + mt * 16;
      abase[mt] = r * 128;
      axor[mt] = (r & 7) << 4;
    }
    int br = wn * 32 + ((lane >> 4) << 3) + (lane & 7);
#pragma unroll
    for (int np = 0; np < 2; np++) {
      int r = br + np * 16;
      bbase[np] = G1_OFF_B + r * 128;
      bxor[np] = (r & 7) << 4;
    }
  }
  uint32_t acs = lane >> 4, bcs = (lane >> 3) & 1;

  CP_WAIT0();
  __syncthreads();

  float acc[4][4][4] = {};
#pragma unroll
  for (int ks = 0; ks < 8; ks++) {
    uint32_t ho = (uint32_t)(ks >> 2) << 14;
    uint32_t ksl = ks & 3;
    uint32_t a[4][4], b[2][4];
#pragma unroll
    for (int np = 0; np < 2; np++)
      ldsm4(b[np], sb + bbase[np] + ho + ((((ksl * 2 + bcs) << 4)) ^ bxor[np]));
#pragma unroll
    for (int mt = 0; mt < 4; mt++)
      ldsm4(a[mt], sb + abase[mt] + ho + ((((ksl * 2 + acs) << 4)) ^ axor[mt]));
#pragma unroll
    for (int mt = 0; mt < 4; mt++)
#pragma unroll
      for (int nt = 0; nt < 4; nt++)
        mma16816(acc[mt][nt], a[mt], &b[nt >> 1][(nt & 1) * 2]);
  }
  __syncthreads();

  float* stg = (float*)smem;
  frag_to_stg(stg, acc, wm, wn, lane);
  __syncthreads();

  // ---- epilogue: bias + GELU + sumsq + fp16 store (coalesced) ----
  float ss[8] = {0, 0, 0, 0, 0, 0, 0, 0};
  int ci = (tid & 15) * 8;
  float4 bb0 = *(const float4*)&b1[n0 + ci];
  float4 bb1 = *(const float4*)&b1[n0 + ci + 4];
  float bias[8] = {bb0.x, bb0.y, bb0.z, bb0.w, bb1.x, bb1.y, bb1.z, bb1.w};
#pragma unroll
  for (int p = 0; p < 8; p++) {
    int rr = p * 16 + (tid >> 4);
    int m = m0 + rr;
    if (m < N_SITES) {
      float4 v0 = *(float4*)&stg[rr * STG_STRIDE + ci];
      float4 v1 = *(float4*)&stg[rr * STG_STRIDE + ci + 4];
      float v[8] = {v0.x, v0.y, v0.z, v0.w, v1.x, v1.y, v1.z, v1.w};
      float gv[8];
#pragma unroll
      for (int e = 0; e < 8; e++) {
        float x = v[e] + bias[e];
        float g = 0.5f * x * (1.f + erff(x * 0.70710678118654752f));
        ss[e] += g * g;
        gv[e] = g;
      }
      union { __half2 h[4]; uint4 u; } uh;
#pragma unroll
      for (int e = 0; e < 4; e++) uh.h[e] = __floats2half2_rn(gv[2 * e], gv[2 * e + 1]);
      *(uint4*)&g_h[(size_t)m * HID + n0 + ci] = uh.u;
    }
  }
#pragma unroll
  for (int e = 0; e < 8; e++) ss[e] += __shfl_xor_sync(0xffffffffu, ss[e], 16);
  if (lane < 16) {
#pragma unroll
    for (int e = 0; e < 8; e++) atomicAdd(&s_ss[ci + e], ss[e]);
  }
  __syncthreads();
  if (tid < 128) atomicAdd(&g_sumsq[n0 + tid], s_ss[tid]);
}

// ---------------------------------------------------------------------------
// GRN scale: scale[c] = grn_g[c] * nx[c] + 1
// ---------------------------------------------------------------------------
__global__ __launch_bounds__(512) void k_grn(const float* __restrict__ grn_g) {
  int t = threadIdx.x;
  float gx = sqrtf(g_sumsq[t]);
  __shared__ float red[16];
  float s = gx;
#pragma unroll
  for (int o = 16; o > 0; o >>= 1) s += __shfl_xor_sync(0xffffffffu, s, o);
  if ((t & 31) == 0) red[t >> 5] = s;
  __syncthreads();
  if (t < 16) {
    float v = red[t];
#pragma unroll
    for (int o = 8; o > 0; o >>= 1) v += __shfl_xor_sync(0x0000ffffu, v, o);
    if (t == 0) red[0] = v;
  }
  __syncthreads();
  float mean = red[0] * (1.f / 512.f);
  g_scale[t] = grn_g[t] * (gx / (mean + 1e-6f)) + 1.f;
}

// Fold: w2s[n][k] = scale[k]*w2[k][n] (fp16); bias2[n] = b2[n] + grn_b @ w2
__global__ __launch_bounds__(128) void k_fold(const float* __restrict__ grn_b,
                                              const float* __restrict__ w2,
                                              const float* __restrict__ b2) {
  int n = blockIdx.x;
  int t = threadIdx.x;
  float part = 0.f;
  for (int kk = t; kk < HID; kk += 128) {
    float wv = w2[kk * DIM + n];
    part += grn_b[kk] * wv;
    g_w2s[n * HID + kk] = __float2half_rn(g_scale[kk] * wv);
  }
  __shared__ float red[4];
#pragma unroll
  for (int o = 16; o > 0; o >>= 1) part += __shfl_xor_sync(0xffffffffu, part, o);
  if ((t & 31) == 0) red[t >> 5] = part;
  __syncthreads();
  if (t == 0) g_bias2[n] = b2[n] + red[0] + red[1] + red[2] + red[3];
}

// ---------------------------------------------------------------------------
// GEMM2: out = (h .* scale) @ w2 + bias2 + feats
// K=512 in 8 chunks of 64, 3-stage cp.async pipeline.
// ---------------------------------------------------------------------------
__global__ __launch_bounds__(256, 2) void k_gemm2(const float* __restrict__ feats,
                                                  float* __restrict__ out) {
  extern __shared__ char smem[];
  uint32_t sb = smem_u32(smem);
  int tid = threadIdx.x, lane = tid & 31, w = tid >> 5;
  int wm = w & 1, wn = w >> 1;
  int m0 = blockIdx.x * 128;

  uint32_t abase[4], axor[4], bbase[2], bxor[2];
  {
    int ar = wm * 64 + (lane & 15);
#pragma unroll
    for (int mt = 0; mt < 4; mt++) {
      int r = ar + mt * 16;
      abase[mt] = r * 128;
      axor[mt] = (r & 7) << 4;
    }
    int br = wn * 32 + ((lane >> 4) << 3) + (lane & 7);
#pragma unroll
    for (int np = 0; np < 2; np++) {
      int r = br + np * 16;
      bbase[np] = G2_OFF_B + r * 128;
      bxor[np] = (r & 7) << 4;
    }
  }
  uint32_t acs = lane >> 4, bcs = (lane >> 3) & 1;

  // per-thread load coords
  int lr = tid >> 3, lc = tid & 7;
  uint32_t lsw = ((lc ^ (lr & 7)) << 4);

  float acc[4][4][4] = {};
  const int CH = HID / 64;  // 8

#pragma unroll
  for (int c = 0; c < 2; c++) {
    uint32_t ssb = sb + c * G2_STAGE;
    int k0 = c * 64;
#pragma unroll
    for (int i = 0; i < 4; i++) {
      int r = lr + i * 32;
      int gr = m0 + r;
      uint32_t sz = (gr < N_SITES) ? 16u : 0u;
      int grc = (gr < N_SITES) ? gr : 0;
      cpa16(ssb + r * 128 + (((lc ^ (r & 7))) << 4), g_h + (size_t)grc * HID + k0 + lc * 8, sz);
      cpa16(ssb + G2_OFF_B + r * 128 + (((lc ^ (r & 7))) << 4),
            g_w2s + (size_t)r * HID + k0 + lc * 8, 16);
    }
    CP_COMMIT();
  }
#pragma unroll 1
  for (int c = 0; c < CH; c++) {
    CP_WAIT1();
    __syncthreads();
    uint32_t ssb = sb + (c % 3) * G2_STAGE;
#pragma unroll
    for (int ks = 0; ks < 4; ks++) {
      uint32_t a[4][4], b[2][4];
#pragma unroll
      for (int np = 0; np < 2; np++)
        ldsm4(b[np], ssb + bbase[np] + ((((ks * 2 + bcs) << 4)) ^ bxor[np]));
#pragma unroll
      for (int mt = 0; mt < 4; mt++)
        ldsm4(a[mt], ssb + abase[mt] + ((((ks * 2 + acs) << 4)) ^ axor[mt]));
#pragma unroll
      for (int mt = 0; mt < 4; mt++)
#pragma unroll
        for (int nt = 0; nt < 4; nt++)
          mma16816(acc[mt][nt], a[mt], &b[nt >> 1][(nt & 1) * 2]);
    }
    int pc = c + 2;
    if (pc < CH) {
      uint32_t psb = sb + (pc % 3) * G2_STAGE;
      int k0 = pc * 64;
#pragma unroll
      for (int i = 0; i < 4; i++) {
        int r = lr + i * 32;
        int gr = m0 + r;
        uint32_t sz = (gr < N_SITES) ? 16u : 0u;
        int grc = (gr < N_SITES) ? gr : 0;
        cpa16(psb + r * 128 + (((lc ^ (r & 7))) << 4), g_h + (size_t)grc * HID + k0 + lc * 8, sz);
        cpa16(psb + G2_OFF_B + r * 128 + (((lc ^ (r & 7))) << 4),
              g_w2s + (size_t)r * HID + k0 + lc * 8, 16);
      }
    }
    CP_COMMIT();
  }
  CP_WAIT0();
  __syncthreads();

  float* stg = (float*)smem;
  frag_to_stg(stg, acc, wm, wn, lane);
  __syncthreads();

  int ci = (tid & 15) * 8;
  float4 bb0 = *(const float4*)&g_bias2[ci];
  float4 bb1 = *(const float4*)&g_bias2[ci + 4];
#pragma unroll
  for (int p = 0; p < 8; p++) {
    int rr = p * 16 + (tid >> 4);
    int m = m0 + rr;
    if (m < N_SITES) {
      float4 v0 = *(float4*)&stg[rr * STG_STRIDE + ci];
      float4 v1 = *(float4*)&stg[rr * STG_STRIDE + ci + 4];
      float4 f0 = *(const float4*)&feats[(size_t)m * DIM + ci];
      float4 f1 = *(const float4*)&feats[(size_t)m * DIM + ci + 4];
      float4 o0, o1;
      o0.x = v0.x + bb0.x + f0.x; o0.y = v0.y + bb0.y + f0.y;
      o0.z = v0.z + bb0.z + f0.z; o0.w = v0.w + bb0.w + f0.w;
      o1.x = v1.x + bb1.x + f1.x; o1.y = v1.y + bb1.y + f1.y;
      o1.z = v1.z + bb1.z + f1.z; o1.w = v1.w + bb1.w + f1.w;
      *(float4*)&out[(size_t)m * DIM + ci] = o0;
      *(float4*)&out[(size_t)m * DIM + ci + 4] = o1;
    }
  }
}

// ---------------------------------------------------------------------------
extern "C" void kernel_launch(void* const* d_in, const int* in_sizes, int n_in,
                              void* d_out, int out_size) {
  const float* feats = (const float*)d_in[0];
  const int* nidx = (const int*)d_in[1];
  const float* dw_w = (const float*)d_in[2];
  const float* dw_b = (const float*)d_in[3];
  const float* ln_g = (const float*)d_in[4];
  const float* ln_b = (const float*)d_in[5];
  const float* w1 = (const float*)d_in[6];
  const float* b1 = (const float*)d_in[7];
  const float* grn_g = (const float*)d_in[8];
  const float* grn_b = (const float*)d_in[9];
  const float* w2 = (const float*)d_in[10];
  const float* b2 = (const float*)d_in[11];
  float* out = (float*)d_out;

  cudaFuncSetAttribute(k_gemm1, cudaFuncAttributeMaxDynamicSharedMemorySize, G1_SMEM);
  cudaFuncSetAttribute(k_gemm2, cudaFuncAttributeMaxDynamicSharedMemorySize, G2_SMEM);

  const int MT = (N_SITES + 127) / 128;  // 782
  k_prepw1<<<256, 256>>>(w1);
  k_dwln<<<N_SITES, 128>>>(feats, nidx, dw_w, dw_b, ln_g, ln_b);
  k_zero<<<1, HID>>>();
  k_gemm1<<<dim3(MT, HID / 128), 256, G1_SMEM>>>(b1);
  k_grn<<<1, HID>>>(grn_g);
  k_fold<<<DIM, 128>>>(grn_b, w2, b2);
  k_gemm2<<<MT, 256, G2_SMEM>>>(feats, out);
}

// round 7
// speedup vs baseline: 2.5757x; 1.0912x over previous
#include <cuda_runtime.h>
#include <cuda_fp16.h>
#include <math.h>
#include <stdint.h>

#define N_SITES 100000
#define DIM 128
#define HID 512
#define KVOL 343

// ---------------- scratch (device globals; no runtime allocation) ----------
__device__ __align__(16) __half g_x[N_SITES * DIM];            // LN output
__device__ __align__(16) __half g_h[(size_t)N_SITES * HID];    // GELU output
__device__ __align__(16) __half g_w1t[HID * DIM];              // w1 transposed [n][k]
__device__ __align__(16) __half g_w2s[DIM * HID];              // scaled w2 [n][k]
__device__ float g_sumsq[HID];
__device__ float g_scale[HID];
__device__ float g_bias2[DIM];

// ---------------- PTX helpers ----------------------------------------------
__device__ __forceinline__ uint32_t smem_u32(const void* p) {
  uint32_t a;
  asm("{ .reg .u64 t; cvta.to.shared.u64 t, %1; cvt.u32.u64 %0, t; }"
      : "=r"(a) : "l"(p));
  return a;
}

__device__ __forceinline__ void cpa16(uint32_t dst, const void* src, uint32_t sz) {
  asm volatile("cp.async.cg.shared.global [%0], [%1], 16, %2;"
               ::"r"(dst), "l"(src), "r"(sz) : "memory");
}
#define CP_COMMIT() asm volatile("cp.async.commit_group;" ::: "memory")
#define CP_WAIT1() asm volatile("cp.async.wait_group 1;" ::: "memory")
#define CP_WAIT0() asm volatile("cp.async.wait_group 0;" ::: "memory")

__device__ __forceinline__ void ldsm4(uint32_t* r, uint32_t addr) {
  asm volatile("ldmatrix.sync.aligned.m8n8.x4.shared.b16 {%0,%1,%2,%3}, [%4];"
               : "=r"(r[0]), "=r"(r[1]), "=r"(r[2]), "=r"(r[3]) : "r"(addr));
}

__device__ __forceinline__ void stsm4(uint32_t addr, uint32_t r0, uint32_t r1,
                                      uint32_t r2, uint32_t r3) {
  asm volatile("stmatrix.sync.aligned.m8n8.x4.shared.b16 [%0], {%1,%2,%3,%4};"
               ::"r"(addr), "r"(r0), "r"(r1), "r"(r2), "r"(r3) : "memory");
}

__device__ __forceinline__ void mma16816(float* d, const uint32_t* a, const uint32_t* b) {
  asm volatile(
      "mma.sync.aligned.m16n8k16.row.col.f32.f16.f16.f32 "
      "{%0,%1,%2,%3}, {%4,%5,%6,%7}, {%8,%9}, {%0,%1,%2,%3};"
      : "+f"(d[0]), "+f"(d[1]), "+f"(d[2]), "+f"(d[3])
      : "r"(a[0]), "r"(a[1]), "r"(a[2]), "r"(a[3]), "r"(b[0]), "r"(b[1]));
}

// ---------------- tiling ----------------------------------------------------
#define STG_STRIDE 132   // fp32 epilogue stage (gemm2)
#define STG_HB 272       // fp16 epilogue stage row bytes (gemm1): 136 halfs
#define G1_OFF_B 32768
#define G1_SMEM 67584
#define G2_STAGE 32768
#define G2_OFF_B 16384
#define G2_SMEM 98304

// ---------------------------------------------------------------------------
// Kernel 1: sparse depthwise conv + LayerNorm -> fp16
// Deterministic ballot/prefix compaction (no atomics).
// ---------------------------------------------------------------------------
__global__ __launch_bounds__(128) void k_dwln(
    const float* __restrict__ feats, const int* __restrict__ nidx,
    const float* __restrict__ dw_w, const float* __restrict__ dw_b,
    const float* __restrict__ ln_g, const float* __restrict__ ln_b) {
  int site = blockIdx.x;
  int tid = threadIdx.x;
  int w = tid >> 5, lane = tid & 31;
  __shared__ int s_k[KVOL];
  __shared__ int s_i[KVOL];
  __shared__ uint32_t s_mask[12];
  __shared__ int s_base[12];
  const int* row = nidx + (size_t)site * KVOL;
  // pass 1: validity masks
#pragma unroll
  for (int it = 0; it < 3; it++) {
    int k = it * 128 + tid;
    bool valid = (k < KVOL) && (row[k] < N_SITES);
    uint32_t m = __ballot_sync(0xffffffffu, valid);
    if (lane == 0) s_mask[it * 4 + w] = m;
  }
  __syncthreads();
  if (tid == 0) {
    int b = 0;
#pragma unroll
    for (int i = 0; i < 12; i++) { s_base[i] = b; b += __popc(s_mask[i]); }
  }
  __syncthreads();
  // pass 2: deterministic scatter
#pragma unroll
  for (int it = 0; it < 3; it++) {
    int k = it * 128 + tid;
    if (k < KVOL) {
      int idx = row[k];
      if (idx < N_SITES) {
        uint32_t m = s_mask[it * 4 + w];
        int pos = s_base[it * 4 + w] + __popc(m & ((1u << lane) - 1u));
        s_k[pos] = k;
        s_i[pos] = idx;
      }
    }
  }
  __syncthreads();
  int cnt = s_base[11] + __popc(s_mask[11]);

  float acc = dw_b[tid];
  for (int v = 0; v < cnt; v++) {
    int k = s_k[v];
    int idx = s_i[v];
    acc += __ldg(&feats[(size_t)idx * DIM + tid]) * dw_w[k * DIM + tid];
  }
  float s1 = acc, s2 = acc * acc;
#pragma unroll
  for (int o = 16; o > 0; o >>= 1) {
    s1 += __shfl_xor_sync(0xffffffffu, s1, o);
    s2 += __shfl_xor_sync(0xffffffffu, s2, o);
  }
  __shared__ float r1[4], r2[4];
  if (lane == 0) { r1[w] = s1; r2[w] = s2; }
  __syncthreads();
  s1 = r1[0] + r1[1] + r1[2] + r1[3];
  s2 = r2[0] + r2[1] + r2[2] + r2[3];
  float mu = s1 * (1.f / 128.f);
  float var = s2 * (1.f / 128.f) - mu * mu;
  float rstd = rsqrtf(var + 1e-6f);
  float val = (acc - mu) * rstd * ln_g[tid] + ln_b[tid];
  g_x[site * DIM + tid] = __float2half_rn(val);
}

// w1 [128,512] -> transposed fp16 w1t [n][k]; block 0 zeros g_sumsq
__global__ __launch_bounds__(256) void k_prepw1(const float* __restrict__ w1) {
  if (blockIdx.x == 0) {
    g_sumsq[threadIdx.x] = 0.f;
    g_sumsq[threadIdx.x + 256] = 0.f;
  }
  int i = blockIdx.x * 256 + threadIdx.x;  // 0..65535
  int n = i >> 7, k = i & 127;
  g_w1t[i] = __float2half_rn(w1[k * HID + n]);
}

// ---------------------------------------------------------------------------
// GEMM1: h = GELU(x @ w1 + b1)  (+ per-channel sumsq for GRN)
// Monolithic K=128; fragment-space epilogue; stmatrix fp16 staging.
// ---------------------------------------------------------------------------
__global__ __launch_bounds__(256, 2) void k_gemm1(const float* __restrict__ b1) {
  extern __shared__ char smem[];
  __shared__ float s_ss[128];
  uint32_t sb = smem_u32(smem);
  int tid = threadIdx.x, lane = tid & 31, w = tid >> 5;
  int wm = w & 1, wn = w >> 1;
  int m0 = blockIdx.x * 128, n0 = blockIdx.y * 128;
  if (tid < 128) s_ss[tid] = 0.f;

  // ---- load A (x[m0..], 128x128 fp16) and B (w1t[n0..]) ----
#pragma unroll
  for (int i = 0; i < 8; i++) {
    int g = i * 256 + tid;
    int r = g >> 4, c16 = g & 15;
    uint32_t dst = sb + ((uint32_t)(c16 >> 3) << 14) + r * 128 + (((c16 & 7) ^ (r & 7)) << 4);
    int gr = m0 + r;
    uint32_t sz = (gr < N_SITES) ? 16u : 0u;
    int grc = (gr < N_SITES) ? gr : 0;
    cpa16(dst, g_x + (size_t)grc * DIM + c16 * 8, sz);
  }
#pragma unroll
  for (int i = 0; i < 8; i++) {
    int g = i * 256 + tid;
    int r = g >> 4, c16 = g & 15;
    uint32_t dst = sb + G1_OFF_B + ((uint32_t)(c16 >> 3) << 14) + r * 128 +
                   (((c16 & 7) ^ (r & 7)) << 4);
    cpa16(dst, g_w1t + (size_t)(n0 + r) * DIM + c16 * 8, 16);
  }
  CP_COMMIT();

  // ---- ldsm offset precompute ----
  uint32_t abase[4], axor[4], bbase[2], bxor[2];
  {
    int ar = wm * 64 + (lane & 15);
#pragma unroll
    for (int mt = 0; mt < 4; mt++) {
      int r = ar + mt * 16;
      abase[mt] = r * 128;
      axor[mt] = (r & 7) << 4;
    }
    int br = wn * 32 + ((lane >> 4) << 3) + (lane & 7);
#pragma unroll
    for (int np = 0; np < 2; np++) {
      int r = br + np * 16;
      bbase[np] = G1_OFF_B + r * 128;
      bxor[np] = (r & 7) << 4;
    }
  }
  uint32_t acs = lane >> 4, bcs = (lane >> 3) & 1;

  CP_WAIT0();
  __syncthreads();

  float acc[4][4][4] = {};
#pragma unroll
  for (int ks = 0; ks < 8; ks++) {
    uint32_t ho = (uint32_t)(ks >> 2) << 14;
    uint32_t ksl = ks & 3;
    uint32_t a[4][4], b[2][4];
#pragma unroll
    for (int np = 0; np < 2; np++)
      ldsm4(b[np], sb + bbase[np] + ho + ((((ksl * 2 + bcs) << 4)) ^ bxor[np]));
#pragma unroll
    for (int mt = 0; mt < 4; mt++)
      ldsm4(a[mt], sb + abase[mt] + ho + ((((ksl * 2 + acs) << 4)) ^ axor[mt]));
#pragma unroll
    for (int mt = 0; mt < 4; mt++)
#pragma unroll
      for (int nt = 0; nt < 4; nt++)
        mma16816(acc[mt][nt], a[mt], &b[nt >> 1][(nt & 1) * 2]);
  }
  __syncthreads();

  // ---- fragment-space epilogue: bias + GELU + sumsq, stmatrix fp16 stage ---
  float2 b_r[4];
#pragma unroll
  for (int nt = 0; nt < 4; nt++)
    b_r[nt] = *(const float2*)&b1[n0 + wn * 32 + nt * 8 + (lane & 3) * 2];

  float ss[8] = {0, 0, 0, 0, 0, 0, 0, 0};
  // stmatrix base address for this lane (matrix = lane>>3, row = lane&7)
  uint32_t st_base = sb + (uint32_t)(wm * 64 + (lane & 7)) * STG_HB +
                     (uint32_t)(wn * 32 + ((lane >> 3) << 3)) * 2;
#pragma unroll
  for (int mt = 0; mt < 4; mt++) {
    int r0 = m0 + wm * 64 + mt * 16 + (lane >> 2);
    float ok0 = (r0 < N_SITES) ? 1.f : 0.f;
    float ok1 = (r0 + 8 < N_SITES) ? 1.f : 0.f;
    uint32_t p01[4], p23[4];
#pragma unroll
    for (int nt = 0; nt < 4; nt++) {
      float x0 = acc[mt][nt][0] + b_r[nt].x;
      float x1 = acc[mt][nt][1] + b_r[nt].y;
      float x2 = acc[mt][nt][2] + b_r[nt].x;
      float x3 = acc[mt][nt][3] + b_r[nt].y;
      float g0 = ok0 * 0.5f * x0 * (1.f + erff(x0 * 0.70710678118654752f));
      float g1 = ok0 * 0.5f * x1 * (1.f + erff(x1 * 0.70710678118654752f));
      float g2 = ok1 * 0.5f * x2 * (1.f + erff(x2 * 0.70710678118654752f));
      float g3 = ok1 * 0.5f * x3 * (1.f + erff(x3 * 0.70710678118654752f));
      ss[nt * 2] += g0 * g0 + g2 * g2;
      ss[nt * 2 + 1] += g1 * g1 + g3 * g3;
      union { __half2 h; uint32_t u; } u01, u23;
      u01.h = __floats2half2_rn(g0, g1);
      u23.h = __floats2half2_rn(g2, g3);
      p01[nt] = u01.u;
      p23[nt] = u23.u;
    }
    uint32_t a0 = st_base + (uint32_t)(mt * 16) * STG_HB;
    stsm4(a0, p01[0], p01[1], p01[2], p01[3]);
    stsm4(a0 + 8 * STG_HB, p23[0], p23[1], p23[2], p23[3]);
  }
  // column-sum reduce: lanes sharing (lane&3) sum via xor shuffles
#pragma unroll
  for (int e = 0; e < 8; e++) {
    ss[e] += __shfl_xor_sync(0xffffffffu, ss[e], 4);
    ss[e] += __shfl_xor_sync(0xffffffffu, ss[e], 8);
    ss[e] += __shfl_xor_sync(0xffffffffu, ss[e], 16);
  }
  if (lane < 4) {
#pragma unroll
    for (int nt = 0; nt < 4; nt++) {
      atomicAdd(&s_ss[wn * 32 + nt * 8 + (lane & 3) * 2], ss[nt * 2]);
      atomicAdd(&s_ss[wn * 32 + nt * 8 + (lane & 3) * 2 + 1], ss[nt * 2 + 1]);
    }
  }
  __syncthreads();

  // ---- coalesced copy: fp16 stage -> g_h ----
  uint32_t ci = (tid & 15) * 16;  // bytes within row
#pragma unroll
  for (int p = 0; p < 8; p++) {
    int rr = p * 16 + (tid >> 4);
    int m = m0 + rr;
    if (m < N_SITES) {
      uint4 v = *(uint4*)(smem + rr * STG_HB + ci);
      *(uint4*)&g_h[(size_t)m * HID + n0 + (tid & 15) * 8] = v;
    }
  }
  if (tid < 128) atomicAdd(&g_sumsq[n0 + tid], s_ss[tid]);
}

// ---------------------------------------------------------------------------
// GRN scale: scale[c] = grn_g[c] * nx[c] + 1
// ---------------------------------------------------------------------------
__global__ __launch_bounds__(512) void k_grn(const float* __restrict__ grn_g) {
  int t = threadIdx.x;
  float gx = sqrtf(g_sumsq[t]);
  __shared__ float red[16];
  float s = gx;
#pragma unroll
  for (int o = 16; o > 0; o >>= 1) s += __shfl_xor_sync(0xffffffffu, s, o);
  if ((t & 31) == 0) red[t >> 5] = s;
  __syncthreads();
  if (t < 16) {
    float v = red[t];
#pragma unroll
    for (int o = 8; o > 0; o >>= 1) v += __shfl_xor_sync(0x0000ffffu, v, o);
    if (t == 0) red[0] = v;
  }
  __syncthreads();
  float mean = red[0] * (1.f / 512.f);
  g_scale[t] = grn_g[t] * (gx / (mean + 1e-6f)) + 1.f;
}

// Fold: w2s[n][k] = scale[k]*w2[k][n] (fp16); bias2[n] = b2[n] + grn_b @ w2
__global__ __launch_bounds__(128) void k_fold(const float* __restrict__ grn_b,
                                              const float* __restrict__ w2,
                                              const float* __restrict__ b2) {
  int n = blockIdx.x;
  int t = threadIdx.x;
  float part = 0.f;
  for (int kk = t; kk < HID; kk += 128) {
    float wv = w2[kk * DIM + n];
    part += grn_b[kk] * wv;
    g_w2s[n * HID + kk] = __float2half_rn(g_scale[kk] * wv);
  }
  __shared__ float red[4];
#pragma unroll
  for (int o = 16; o > 0; o >>= 1) part += __shfl_xor_sync(0xffffffffu, part, o);
  if ((t & 31) == 0) red[t >> 5] = part;
  __syncthreads();
  if (t == 0) g_bias2[n] = b2[n] + red[0] + red[1] + red[2] + red[3];
}

// ---------------------------------------------------------------------------
// GEMM2: out = (h .* scale) @ w2 + bias2 + feats
// K=512 in 8 chunks of 64, 3-stage cp.async pipeline.
// ---------------------------------------------------------------------------
__global__ __launch_bounds__(256, 2) void k_gemm2(const float* __restrict__ feats,
                                                  float* __restrict__ out) {
  extern __shared__ char smem[];
  uint32_t sb = smem_u32(smem);
  int tid = threadIdx.x, lane = tid & 31, w = tid >> 5;
  int wm = w & 1, wn = w >> 1;
  int m0 = blockIdx.x * 128;

  uint32_t abase[4], axor[4], bbase[2], bxor[2];
  {
    int ar = wm * 64 + (lane & 15);
#pragma unroll
    for (int mt = 0; mt < 4; mt++) {
      int r = ar + mt * 16;
      abase[mt] = r * 128;
      axor[mt] = (r & 7) << 4;
    }
    int br = wn * 32 + ((lane >> 4) << 3) + (lane & 7);
#pragma unroll
    for (int np = 0; np < 2; np++) {
      int r = br + np * 16;
      bbase[np] = G2_OFF_B + r * 128;
      bxor[np] = (r & 7) << 4;
    }
  }
  uint32_t acs = lane >> 4, bcs = (lane >> 3) & 1;

  int lr = tid >> 3, lc = tid & 7;

  float acc[4][4][4] = {};
  const int CH = HID / 64;  // 8

#pragma unroll
  for (int c = 0; c < 2; c++) {
    uint32_t ssb = sb + c * G2_STAGE;
    int k0 = c * 64;
#pragma unroll
    for (int i = 0; i < 4; i++) {
      int r = lr + i * 32;
      int gr = m0 + r;
      uint32_t sz = (gr < N_SITES) ? 16u : 0u;
      int grc = (gr < N_SITES) ? gr : 0;
      cpa16(ssb + r * 128 + (((lc ^ (r & 7))) << 4), g_h + (size_t)grc * HID + k0 + lc * 8, sz);
      cpa16(ssb + G2_OFF_B + r * 128 + (((lc ^ (r & 7))) << 4),
            g_w2s + (size_t)r * HID + k0 + lc * 8, 16);
    }
    CP_COMMIT();
  }
#pragma unroll 1
  for (int c = 0; c < CH; c++) {
    CP_WAIT1();
    __syncthreads();
    uint32_t ssb = sb + (c % 3) * G2_STAGE;
#pragma unroll
    for (int ks = 0; ks < 4; ks++) {
      uint32_t a[4][4], b[2][4];
#pragma unroll
      for (int np = 0; np < 2; np++)
        ldsm4(b[np], ssb + bbase[np] + ((((ks * 2 + bcs) << 4)) ^ bxor[np]));
#pragma unroll
      for (int mt = 0; mt < 4; mt++)
        ldsm4(a[mt], ssb + abase[mt] + ((((ks * 2 + acs) << 4)) ^ axor[mt]));
#pragma unroll
      for (int mt = 0; mt < 4; mt++)
#pragma unroll
        for (int nt = 0; nt < 4; nt++)
          mma16816(acc[mt][nt], a[mt], &b[nt >> 1][(nt & 1) * 2]);
    }
    int pc = c + 2;
    if (pc < CH) {
      uint32_t psb = sb + (pc % 3) * G2_STAGE;
      int k0 = pc * 64;
#pragma unroll
      for (int i = 0; i < 4; i++) {
        int r = lr + i * 32;
        int gr = m0 + r;
        uint32_t sz = (gr < N_SITES) ? 16u : 0u;
        int grc = (gr < N_SITES) ? gr : 0;
        cpa16(psb + r * 128 + (((lc ^ (r & 7))) << 4), g_h + (size_t)grc * HID + k0 + lc * 8, sz);
        cpa16(psb + G2_OFF_B + r * 128 + (((lc ^ (r & 7))) << 4),
              g_w2s + (size_t)r * HID + k0 + lc * 8, 16);
      }
    }
    CP_COMMIT();
  }
  CP_WAIT0();
  __syncthreads();

  float* stg = (float*)smem;
#pragma unroll
  for (int mt = 0; mt < 4; mt++)
#pragma unroll
    for (int nt = 0; nt < 4; nt++) {
      int m = wm * 64 + mt * 16 + (lane >> 2);
      int n = wn * 32 + nt * 8 + (lane & 3) * 2;
      *(float2*)&stg[m * STG_STRIDE + n] = make_float2(acc[mt][nt][0], acc[mt][nt][1]);
      *(float2*)&stg[(m + 8) * STG_STRIDE + n] = make_float2(acc[mt][nt][2], acc[mt][nt][3]);
    }
  __syncthreads();

  int ci = (tid & 15) * 8;
  float4 bb0 = *(const float4*)&g_bias2[ci];
  float4 bb1 = *(const float4*)&g_bias2[ci + 4];
#pragma unroll
  for (int p = 0; p < 8; p++) {
    int rr = p * 16 + (tid >> 4);
    int m = m0 + rr;
    if (m < N_SITES) {
      float4 v0 = *(float4*)&stg[rr * STG_STRIDE + ci];
      float4 v1 = *(float4*)&stg[rr * STG_STRIDE + ci + 4];
      float4 f0 = *(const float4*)&feats[(size_t)m * DIM + ci];
      float4 f1 = *(const float4*)&feats[(size_t)m * DIM + ci + 4];
      float4 o0, o1;
      o0.x = v0.x + bb0.x + f0.x; o0.y = v0.y + bb0.y + f0.y;
      o0.z = v0.z + bb0.z + f0.z; o0.w = v0.w + bb0.w + f0.w;
      o1.x = v1.x + bb1.x + f1.x; o1.y = v1.y + bb1.y + f1.y;
      o1.z = v1.z + bb1.z + f1.z; o1.w = v1.w + bb1.w + f1.w;
      *(float4*)&out[(size_t)m * DIM + ci] = o0;
      *(float4*)&out[(size_t)m * DIM + ci + 4] = o1;
    }
  }
}

// ---------------------------------------------------------------------------
extern "C" void kernel_launch(void* const* d_in, const int* in_sizes, int n_in,
                              void* d_out, int out_size) {
  const float* feats = (const float*)d_in[0];
  const int* nidx = (const int*)d_in[1];
  const float* dw_w = (const float*)d_in[2];
  const float* dw_b = (const float*)d_in[3];
  const float* ln_g = (const float*)d_in[4];
  const float* ln_b = (const float*)d_in[5];
  const float* w1 = (const float*)d_in[6];
  const float* b1 = (const float*)d_in[7];
  const float* grn_g = (const float*)d_in[8];
  const float* grn_b = (const float*)d_in[9];
  const float* w2 = (const float*)d_in[10];
  const float* b2 = (const float*)d_in[11];
  float* out = (float*)d_out;

  cudaFuncSetAttribute(k_gemm1, cudaFuncAttributeMaxDynamicSharedMemorySize, G1_SMEM);
  cudaFuncSetAttribute(k_gemm2, cudaFuncAttributeMaxDynamicSharedMemorySize, G2_SMEM);

  const int MT = (N_SITES + 127) / 128;  // 782
  k_prepw1<<<256, 256>>>(w1);
  k_dwln<<<N_SITES, 128>>>(feats, nidx, dw_w, dw_b, ln_g, ln_b);
  k_gemm1<<<dim3(MT, HID / 128), 256, G1_SMEM>>>(b1);
  k_grn<<<1, HID>>>(grn_g);
  k_fold<<<DIM, 128>>>(grn_b, w2, b2);
  k_gemm2<<<MT, 256, G2_SMEM>>>(feats, out);
}

// round 8
// speedup vs baseline: 3.3513x; 1.3011x over previous
#include <cuda_runtime.h>
#include <cuda_fp16.h>
#include <math.h>
#include <stdint.h>

#define N_SITES 100000
#define DIM 128
#define HID 512
#define KVOL 343

// ---------------- scratch (device globals; no runtime allocation) ----------
__device__ __align__(16) __half g_x[N_SITES * DIM];            // LN output
__device__ __align__(16) __half g_h[(size_t)N_SITES * HID];    // GELU output
__device__ __align__(16) __half g_w1t[HID * DIM];              // w1 transposed [n][k]
__device__ __align__(16) __half g_w2s[DIM * HID];              // scaled w2 [n][k]
__device__ float g_sumsq[HID];
__device__ float g_bias2[DIM];

// ---------------- PTX helpers ----------------------------------------------
__device__ __forceinline__ uint32_t smem_u32(const void* p) {
  uint32_t a;
  asm("{ .reg .u64 t; cvta.to.shared.u64 t, %1; cvt.u32.u64 %0, t; }"
      : "=r"(a) : "l"(p));
  return a;
}

__device__ __forceinline__ void cpa16(uint32_t dst, const void* src, uint32_t sz) {
  asm volatile("cp.async.cg.shared.global [%0], [%1], 16, %2;"
               ::"r"(dst), "l"(src), "r"(sz) : "memory");
}
#define CP_COMMIT() asm volatile("cp.async.commit_group;" ::: "memory")
#define CP_WAIT1() asm volatile("cp.async.wait_group 1;" ::: "memory")
#define CP_WAIT0() asm volatile("cp.async.wait_group 0;" ::: "memory")

__device__ __forceinline__ void ldsm4(uint32_t* r, uint32_t addr) {
  asm volatile("ldmatrix.sync.aligned.m8n8.x4.shared.b16 {%0,%1,%2,%3}, [%4];"
               : "=r"(r[0]), "=r"(r[1]), "=r"(r[2]), "=r"(r[3]) : "r"(addr));
}

__device__ __forceinline__ void stsm4(uint32_t addr, uint32_t r0, uint32_t r1,
                                      uint32_t r2, uint32_t r3) {
  asm volatile("stmatrix.sync.aligned.m8n8.x4.shared.b16 [%0], {%1,%2,%3,%4};"
               ::"r"(addr), "r"(r0), "r"(r1), "r"(r2), "r"(r3) : "memory");
}

__device__ __forceinline__ void mma16816(float* d, const uint32_t* a, const uint32_t* b) {
  asm volatile(
      "mma.sync.aligned.m16n8k16.row.col.f32.f16.f16.f32 "
      "{%0,%1,%2,%3}, {%4,%5,%6,%7}, {%8,%9}, {%0,%1,%2,%3};"
      : "+f"(d[0]), "+f"(d[1]), "+f"(d[2]), "+f"(d[3])
      : "r"(a[0]), "r"(a[1]), "r"(a[2]), "r"(a[3]), "r"(b[0]), "r"(b[1]));
}

// ---------------- tiling ----------------------------------------------------
#define STG_STRIDE 132   // fp32 epilogue stage (gemm2)
#define STG_HB 272       // fp16 epilogue stage row bytes (gemm1): 136 halfs
#define G1_OFF_B 32768
#define G1_SMEM 67584
#define G2_STAGE 32768
#define G2_OFF_B 16384
#define G2_SMEM 98304

// ---------------------------------------------------------------------------
// Kernel 1: sparse depthwise conv + LayerNorm -> fp16
// One warp per site; float4 per lane; warp-local compaction + LN reduce.
// ---------------------------------------------------------------------------
__global__ __launch_bounds__(256) void k_dwln(
    const float* __restrict__ feats, const int* __restrict__ nidx,
    const float* __restrict__ dw_w, const float* __restrict__ dw_b,
    const float* __restrict__ ln_g, const float* __restrict__ ln_b) {
  int wrp = threadIdx.x >> 5, lane = threadIdx.x & 31;
  int site = blockIdx.x * 8 + wrp;  // 12500 * 8 = 100000 exactly
  __shared__ int s_k[8][344];
  __shared__ int s_i[8][344];
  const int* row = nidx + (size_t)site * KVOL;

  int base = 0;
#pragma unroll
  for (int it = 0; it < 11; it++) {
    int k = it * 32 + lane;
    int idx = (k < KVOL) ? row[k] : N_SITES;
    bool valid = idx < N_SITES;
    uint32_t m = __ballot_sync(0xffffffffu, valid);
    if (valid) {
      int pos = base + __popc(m & ((1u << lane) - 1u));
      s_k[wrp][pos] = k;
      s_i[wrp][pos] = idx;
    }
    base += __popc(m);
  }
  int cnt = base;
  __syncwarp();

  const float4* f4 = (const float4*)feats;
  const float4* w4 = (const float4*)dw_w;
  float4 bb = ((const float4*)dw_b)[lane];
  float a0 = bb.x, a1 = bb.y, a2 = bb.z, a3 = bb.w;
  int v = 0;
  for (; v + 2 <= cnt; v += 2) {
    int ka = s_k[wrp][v], ia = s_i[wrp][v];
    int kb = s_k[wrp][v + 1], ib = s_i[wrp][v + 1];
    float4 fa = __ldg(&f4[(size_t)ia * 32 + lane]);
    float4 wa = __ldg(&w4[(size_t)ka * 32 + lane]);
    float4 fb = __ldg(&f4[(size_t)ib * 32 + lane]);
    float4 wb = __ldg(&w4[(size_t)kb * 32 + lane]);
    a0 += fa.x * wa.x + fb.x * wb.x;
    a1 += fa.y * wa.y + fb.y * wb.y;
    a2 += fa.z * wa.z + fb.z * wb.z;
    a3 += fa.w * wa.w + fb.w * wb.w;
  }
  if (v < cnt) {
    int ka = s_k[wrp][v], ia = s_i[wrp][v];
    float4 fa = __ldg(&f4[(size_t)ia * 32 + lane]);
    float4 wa = __ldg(&w4[(size_t)ka * 32 + lane]);
    a0 += fa.x * wa.x;
    a1 += fa.y * wa.y;
    a2 += fa.z * wa.z;
    a3 += fa.w * wa.w;
  }

  float s1 = a0 + a1 + a2 + a3;
  float s2 = a0 * a0 + a1 * a1 + a2 * a2 + a3 * a3;
#pragma unroll
  for (int o = 16; o > 0; o >>= 1) {
    s1 += __shfl_xor_sync(0xffffffffu, s1, o);
    s2 += __shfl_xor_sync(0xffffffffu, s2, o);
  }
  float mu = s1 * (1.f / 128.f);
  float var = s2 * (1.f / 128.f) - mu * mu;
  float rstd = rsqrtf(var + 1e-6f);
  float4 gg = ((const float4*)ln_g)[lane];
  float4 gb = ((const float4*)ln_b)[lane];
  float v0 = (a0 - mu) * rstd * gg.x + gb.x;
  float v1 = (a1 - mu) * rstd * gg.y + gb.y;
  float v2 = (a2 - mu) * rstd * gg.z + gb.z;
  float v3 = (a3 - mu) * rstd * gg.w + gb.w;
  union { __half2 h[2]; uint2 u; } o;
  o.h[0] = __floats2half2_rn(v0, v1);
  o.h[1] = __floats2half2_rn(v2, v3);
  *(uint2*)&g_x[(size_t)site * DIM + lane * 4] = o.u;
}

// w1 [128,512] -> transposed fp16 w1t [n][k]; block 0 zeros g_sumsq
__global__ __launch_bounds__(256) void k_prepw1(const float* __restrict__ w1) {
  if (blockIdx.x == 0) {
    g_sumsq[threadIdx.x] = 0.f;
    g_sumsq[threadIdx.x + 256] = 0.f;
  }
  int i = blockIdx.x * 256 + threadIdx.x;  // 0..65535
  int n = i >> 7, k = i & 127;
  g_w1t[i] = __float2half_rn(w1[k * HID + n]);
}

// ---------------------------------------------------------------------------
// GEMM1: h = GELU(x @ w1 + b1)  (+ per-channel sumsq for GRN)
// ---------------------------------------------------------------------------
__global__ __launch_bounds__(256, 2) void k_gemm1(const float* __restrict__ b1) {
  extern __shared__ char smem[];
  __shared__ float s_ss[128];
  uint32_t sb = smem_u32(smem);
  int tid = threadIdx.x, lane = tid & 31, w = tid >> 5;
  int wm = w & 1, wn = w >> 1;
  int m0 = blockIdx.x * 128, n0 = blockIdx.y * 128;
  if (tid < 128) s_ss[tid] = 0.f;

#pragma unroll
  for (int i = 0; i < 8; i++) {
    int g = i * 256 + tid;
    int r = g >> 4, c16 = g & 15;
    uint32_t dst = sb + ((uint32_t)(c16 >> 3) << 14) + r * 128 + (((c16 & 7) ^ (r & 7)) << 4);
    int gr = m0 + r;
    uint32_t sz = (gr < N_SITES) ? 16u : 0u;
    int grc = (gr < N_SITES) ? gr : 0;
    cpa16(dst, g_x + (size_t)grc * DIM + c16 * 8, sz);
  }
#pragma unroll
  for (int i = 0; i < 8; i++) {
    int g = i * 256 + tid;
    int r = g >> 4, c16 = g & 15;
    uint32_t dst = sb + G1_OFF_B + ((uint32_t)(c16 >> 3) << 14) + r * 128 +
                   (((c16 & 7) ^ (r & 7)) << 4);
    cpa16(dst, g_w1t + (size_t)(n0 + r) * DIM + c16 * 8, 16);
  }
  CP_COMMIT();

  uint32_t abase[4], axor[4], bbase[2], bxor[2];
  {
    int ar = wm * 64 + (lane & 15);
#pragma unroll
    for (int mt = 0; mt < 4; mt++) {
      int r = ar + mt * 16;
      abase[mt] = r * 128;
      axor[mt] = (r & 7) << 4;
    }
    int br = wn * 32 + ((lane >> 4) << 3) + (lane & 7);
#pragma unroll
    for (int np = 0; np < 2; np++) {
      int r = br + np * 16;
      bbase[np] = G1_OFF_B + r * 128;
      bxor[np] = (r & 7) << 4;
    }
  }
  uint32_t acs = lane >> 4, bcs = (lane >> 3) & 1;

  CP_WAIT0();
  __syncthreads();

  float acc[4][4][4] = {};
#pragma unroll
  for (int ks = 0; ks < 8; ks++) {
    uint32_t ho = (uint32_t)(ks >> 2) << 14;
    uint32_t ksl = ks & 3;
    uint32_t a[4][4], b[2][4];
#pragma unroll
    for (int np = 0; np < 2; np++)
      ldsm4(b[np], sb + bbase[np] + ho + ((((ksl * 2 + bcs) << 4)) ^ bxor[np]));
#pragma unroll
    for (int mt = 0; mt < 4; mt++)
      ldsm4(a[mt], sb + abase[mt] + ho + ((((ksl * 2 + acs) << 4)) ^ axor[mt]));
#pragma unroll
    for (int mt = 0; mt < 4; mt++)
#pragma unroll
      for (int nt = 0; nt < 4; nt++)
        mma16816(acc[mt][nt], a[mt], &b[nt >> 1][(nt & 1) * 2]);
  }
  __syncthreads();

  // ---- fragment-space epilogue ----
  float2 b_r[4];
#pragma unroll
  for (int nt = 0; nt < 4; nt++)
    b_r[nt] = *(const float2*)&b1[n0 + wn * 32 + nt * 8 + (lane & 3) * 2];

  float ss[8] = {0, 0, 0, 0, 0, 0, 0, 0};
  uint32_t st_base = sb + (uint32_t)(wm * 64 + (lane & 7)) * STG_HB +
                     (uint32_t)(wn * 32 + ((lane >> 3) << 3)) * 2;
#pragma unroll
  for (int mt = 0; mt < 4; mt++) {
    int r0 = m0 + wm * 64 + mt * 16 + (lane >> 2);
    float ok0 = (r0 < N_SITES) ? 1.f : 0.f;
    float ok1 = (r0 + 8 < N_SITES) ? 1.f : 0.f;
    uint32_t p01[4], p23[4];
#pragma unroll
    for (int nt = 0; nt < 4; nt++) {
      float x0 = acc[mt][nt][0] + b_r[nt].x;
      float x1 = acc[mt][nt][1] + b_r[nt].y;
      float x2 = acc[mt][nt][2] + b_r[nt].x;
      float x3 = acc[mt][nt][3] + b_r[nt].y;
      float g0 = ok0 * 0.5f * x0 * (1.f + erff(x0 * 0.70710678118654752f));
      float g1 = ok0 * 0.5f * x1 * (1.f + erff(x1 * 0.70710678118654752f));
      float g2 = ok1 * 0.5f * x2 * (1.f + erff(x2 * 0.70710678118654752f));
      float g3 = ok1 * 0.5f * x3 * (1.f + erff(x3 * 0.70710678118654752f));
      ss[nt * 2] += g0 * g0 + g2 * g2;
      ss[nt * 2 + 1] += g1 * g1 + g3 * g3;
      union { __half2 h; uint32_t u; } u01, u23;
      u01.h = __floats2half2_rn(g0, g1);
      u23.h = __floats2half2_rn(g2, g3);
      p01[nt] = u01.u;
      p23[nt] = u23.u;
    }
    uint32_t a0 = st_base + (uint32_t)(mt * 16) * STG_HB;
    stsm4(a0, p01[0], p01[1], p01[2], p01[3]);
    stsm4(a0 + 8 * STG_HB, p23[0], p23[1], p23[2], p23[3]);
  }
#pragma unroll
  for (int e = 0; e < 8; e++) {
    ss[e] += __shfl_xor_sync(0xffffffffu, ss[e], 4);
    ss[e] += __shfl_xor_sync(0xffffffffu, ss[e], 8);
    ss[e] += __shfl_xor_sync(0xffffffffu, ss[e], 16);
  }
  if (lane < 4) {
#pragma unroll
    for (int nt = 0; nt < 4; nt++) {
      atomicAdd(&s_ss[wn * 32 + nt * 8 + (lane & 3) * 2], ss[nt * 2]);
      atomicAdd(&s_ss[wn * 32 + nt * 8 + (lane & 3) * 2 + 1], ss[nt * 2 + 1]);
    }
  }
  __syncthreads();

  uint32_t ci = (tid & 15) * 16;
#pragma unroll
  for (int p = 0; p < 8; p++) {
    int rr = p * 16 + (tid >> 4);
    int m = m0 + rr;
    if (m < N_SITES) {
      uint4 v = *(uint4*)(smem + rr * STG_HB + ci);
      *(uint4*)&g_h[(size_t)m * HID + n0 + (tid & 15) * 8] = v;
    }
  }
  if (tid < 128) atomicAdd(&g_sumsq[n0 + tid], s_ss[tid]);
}

// ---------------------------------------------------------------------------
// Fold (with inline GRN): scale[k] = grn_g[k]*nx[k]+1;
// w2s[n][k] = scale[k]*w2[k][n]; bias2[n] = b2[n] + grn_b @ w2
// ---------------------------------------------------------------------------
__global__ __launch_bounds__(128) void k_fold(const float* __restrict__ grn_g,
                                              const float* __restrict__ grn_b,
                                              const float* __restrict__ w2,
                                              const float* __restrict__ b2) {
  int n = blockIdx.x;
  int t = threadIdx.x;
  // inline GRN: each thread owns channels t, t+128, t+256, t+384
  float gx[4];
  float loc = 0.f;
#pragma unroll
  for (int j = 0; j < 4; j++) {
    gx[j] = sqrtf(g_sumsq[t + j * 128]);
    loc += gx[j];
  }
  __shared__ float red[4];
#pragma unroll
  for (int o = 16; o > 0; o >>= 1) loc += __shfl_xor_sync(0xffffffffu, loc, o);
  if ((t & 31) == 0) red[t >> 5] = loc;
  __syncthreads();
  float mean = (red[0] + red[1] + red[2] + red[3]) * (1.f / 512.f);
  float inv = 1.f / (mean + 1e-6f);

  float part = 0.f;
#pragma unroll
  for (int j = 0; j < 4; j++) {
    int kk = t + j * 128;
    float wv = w2[kk * DIM + n];
    part += grn_b[kk] * wv;
    float scale = grn_g[kk] * (gx[j] * inv) + 1.f;
    g_w2s[n * HID + kk] = __float2half_rn(scale * wv);
  }
#pragma unroll
  for (int o = 16; o > 0; o >>= 1) part += __shfl_xor_sync(0xffffffffu, part, o);
  if ((t & 31) == 0) red[t >> 5] = part;
  __syncthreads();
  if (t == 0) g_bias2[n] = b2[n] + red[0] + red[1] + red[2] + red[3];
}

// ---------------------------------------------------------------------------
// GEMM2: out = (h .* scale) @ w2 + bias2 + feats
// ---------------------------------------------------------------------------
__global__ __launch_bounds__(256, 2) void k_gemm2(const float* __restrict__ feats,
                                                  float* __restrict__ out) {
  extern __shared__ char smem[];
  uint32_t sb = smem_u32(smem);
  int tid = threadIdx.x, lane = tid & 31, w = tid >> 5;
  int wm = w & 1, wn = w >> 1;
  int m0 = blockIdx.x * 128;

  uint32_t abase[4], axor[4], bbase[2], bxor[2];
  {
    int ar = wm * 64 + (lane & 15);
#pragma unroll
    for (int mt = 0; mt < 4; mt++) {
      int r = ar + mt * 16;
      abase[mt] = r * 128;
      axor[mt] = (r & 7) << 4;
    }
    int br = wn * 32 + ((lane >> 4) << 3) + (lane & 7);
#pragma unroll
    for (int np = 0; np < 2; np++) {
      int r = br + np * 16;
      bbase[np] = G2_OFF_B + r * 128;
      bxor[np] = (r & 7) << 4;
    }
  }
  uint32_t acs = lane >> 4, bcs = (lane >> 3) & 1;

  int lr = tid >> 3, lc = tid & 7;

  float acc[4][4][4] = {};
  const int CH = HID / 64;  // 8

#pragma unroll
  for (int c = 0; c < 2; c++) {
    uint32_t ssb = sb + c * G2_STAGE;
    int k0 = c * 64;
#pragma unroll
    for (int i = 0; i < 4; i++) {
      int r = lr + i * 32;
      int gr = m0 + r;
      uint32_t sz = (gr < N_SITES) ? 16u : 0u;
      int grc = (gr < N_SITES) ? gr : 0;
      cpa16(ssb + r * 128 + (((lc ^ (r & 7))) << 4), g_h + (size_t)grc * HID + k0 + lc * 8, sz);
      cpa16(ssb + G2_OFF_B + r * 128 + (((lc ^ (r & 7))) << 4),
            g_w2s + (size_t)r * HID + k0 + lc * 8, 16);
    }
    CP_COMMIT();
  }
#pragma unroll 1
  for (int c = 0; c < CH; c++) {
    CP_WAIT1();
    __syncthreads();
    uint32_t ssb = sb + (c % 3) * G2_STAGE;
#pragma unroll
    for (int ks = 0; ks < 4; ks++) {
      uint32_t a[4][4], b[2][4];
#pragma unroll
      for (int np = 0; np < 2; np++)
        ldsm4(b[np], ssb + bbase[np] + ((((ks * 2 + bcs) << 4)) ^ bxor[np]));
#pragma unroll
      for (int mt = 0; mt < 4; mt++)
        ldsm4(a[mt], ssb + abase[mt] + ((((ks * 2 + acs) << 4)) ^ axor[mt]));
#pragma unroll
      for (int mt = 0; mt < 4; mt++)
#pragma unroll
        for (int nt = 0; nt < 4; nt++)
          mma16816(acc[mt][nt], a[mt], &b[nt >> 1][(nt & 1) * 2]);
    }
    int pc = c + 2;
    if (pc < CH) {
      uint32_t psb = sb + (pc % 3) * G2_STAGE;
      int k0 = pc * 64;
#pragma unroll
      for (int i = 0; i < 4; i++) {
        int r = lr + i * 32;
        int gr = m0 + r;
        uint32_t sz = (gr < N_SITES) ? 16u : 0u;
        int grc = (gr < N_SITES) ? gr : 0;
        cpa16(psb + r * 128 + (((lc ^ (r & 7))) << 4), g_h + (size_t)grc * HID + k0 + lc * 8, sz);
        cpa16(psb + G2_OFF_B + r * 128 + (((lc ^ (r & 7))) << 4),
              g_w2s + (size_t)r * HID + k0 + lc * 8, 16);
      }
    }
    CP_COMMIT();
  }
  CP_WAIT0();
  __syncthreads();

  float* stg = (float*)smem;
#pragma unroll
  for (int mt = 0; mt < 4; mt++)
#pragma unroll
    for (int nt = 0; nt < 4; nt++) {
      int m = wm * 64 + mt * 16 + (lane >> 2);
      int n = wn * 32 + nt * 8 + (lane & 3) * 2;
      *(float2*)&stg[m * STG_STRIDE + n] = make_float2(acc[mt][nt][0], acc[mt][nt][1]);
      *(float2*)&stg[(m + 8) * STG_STRIDE + n] = make_float2(acc[mt][nt][2], acc[mt][nt][3]);
    }
  __syncthreads();

  int ci = (tid & 15) * 8;
  float4 bb0 = *(const float4*)&g_bias2[ci];
  float4 bb1 = *(const float4*)&g_bias2[ci + 4];
#pragma unroll
  for (int p = 0; p < 8; p++) {
    int rr = p * 16 + (tid >> 4);
    int m = m0 + rr;
    if (m < N_SITES) {
      float4 v0 = *(float4*)&stg[rr * STG_STRIDE + ci];
      float4 v1 = *(float4*)&stg[rr * STG_STRIDE + ci + 4];
      float4 f0 = *(const float4*)&feats[(size_t)m * DIM + ci];
      float4 f1 = *(const float4*)&feats[(size_t)m * DIM + ci + 4];
      float4 o0, o1;
      o0.x = v0.x + bb0.x + f0.x; o0.y = v0.y + bb0.y + f0.y;
      o0.z = v0.z + bb0.z + f0.z; o0.w = v0.w + bb0.w + f0.w;
      o1.x = v1.x + bb1.x + f1.x; o1.y = v1.y + bb1.y + f1.y;
      o1.z = v1.z + bb1.z + f1.z; o1.w = v1.w + bb1.w + f1.w;
      *(float4*)&out[(size_t)m * DIM + ci] = o0;
      *(float4*)&out[(size_t)m * DIM + ci + 4] = o1;
    }
  }
}

// ---------------------------------------------------------------------------
extern "C" void kernel_launch(void* const* d_in, const int* in_sizes, int n_in,
                              void* d_out, int out_size) {
  const float* feats = (const float*)d_in[0];
  const int* nidx = (const int*)d_in[1];
  const float* dw_w = (const float*)d_in[2];
  const float* dw_b = (const float*)d_in[3];
  const float* ln_g = (const float*)d_in[4];
  const float* ln_b = (const float*)d_in[5];
  const float* w1 = (const float*)d_in[6];
  const float* b1 = (const float*)d_in[7];
  const float* grn_g = (const float*)d_in[8];
  const float* grn_b = (const float*)d_in[9];
  const float* w2 = (const float*)d_in[10];
  const float* b2 = (const float*)d_in[11];
  float* out = (float*)d_out;

  cudaFuncSetAttribute(k_gemm1, cudaFuncAttributeMaxDynamicSharedMemorySize, G1_SMEM);
  cudaFuncSetAttribute(k_gemm2, cudaFuncAttributeMaxDynamicSharedMemorySize, G2_SMEM);

  const int MT = (N_SITES + 127) / 128;  // 782
  k_prepw1<<<256, 256>>>(w1);
  k_dwln<<<N_SITES / 8, 256>>>(feats, nidx, dw_w, dw_b, ln_g, ln_b);
  k_gemm1<<<dim3(MT, HID / 128), 256, G1_SMEM>>>(b1);
  k_fold<<<DIM, 128>>>(grn_g, grn_b, w2, b2);
  k_gemm2<<<MT, 256, G2_SMEM>>>(feats, out);
}